// round 7
// baseline (speedup 1.0000x reference)
#include <cuda_runtime.h>

// ---------------- problem constants ----------------
#define NGEN  4
#define NSYM  100
// level offsets into x (cumsum of 8*4^l)
#define OFF0 0
#define OFF1 8
#define OFF2 40
#define OFF3 168
#define OFF4 680
#define OFF5 2728
#define OFF6 10920
#define OFF7 43688
#define OFF8 174760
#define DIMX 699048

#define N2 128
#define NBLK 512     // total blocks (4 g x 128)

// ---------------- scratch (static device, no allocs) ----------------
__device__ float g_beta2[(size_t)NGEN * N2 * 8];
__device__ float g_ell2 [(size_t)NGEN * N2];
__device__ unsigned int g_ctr = 0;

// ---------------- helpers ----------------
__device__ __forceinline__ float sum8r(const float v[8]) {
    return ((v[0] + v[1]) + (v[2] + v[3])) + ((v[4] + v[5]) + (v[6] + v[7]));
}

__device__ __forceinline__ float groupSum8(float v) {
    v += __shfl_xor_sync(0xffffffffu, v, 4, 8);
    v += __shfl_xor_sync(0xffffffffu, v, 2, 8);
    v += __shfl_xor_sync(0xffffffffu, v, 1, 8);
    return v;
}

// m_d = sum_c sTj[c*8+d] * bhat_c  (bhat distributed over 8-lane group)
__device__ __forceinline__ float groupMatvec(const float* __restrict__ sTj, float bhat, int d) {
    float m = 0.f;
#pragma unroll
    for (int c = 0; c < 8; ++c) {
        float bc = __shfl_sync(0xffffffffu, bhat, c, 8);
        m = fmaf(sTj[c * 8 + d], bc, m);
    }
    return m;
}

// B softmax for one (g,c) by one warp -> dstBase[sym*12 + c]
__device__ __forceinline__ void bsoftmax_warp(int g, int c, int lane,
                                              const float* __restrict__ Bm,
                                              float* __restrict__ dstBase) {
    const float* src = Bm + c * 400 + g;
    float v0 = src[(lane)      * 4];
    float v1 = src[(lane + 32) * 4];
    float v2 = src[(lane + 64) * 4];
    float v3 = (lane < 4) ? src[(lane + 96) * 4] : -1e30f;
    float mx = fmaxf(fmaxf(v0, v1), fmaxf(v2, v3));
#pragma unroll
    for (int off = 16; off >= 1; off >>= 1)
        mx = fmaxf(mx, __shfl_xor_sync(0xffffffffu, mx, off));
    float e0 = __expf(v0 - mx), e1 = __expf(v1 - mx), e2 = __expf(v2 - mx);
    float e3 = (lane < 4) ? __expf(v3 - mx) : 0.f;
    float s = e0 + e1 + e2 + e3;
#pragma unroll
    for (int off = 16; off >= 1; off >>= 1)
        s += __shfl_xor_sync(0xffffffffu, s, off);
    float inv = 1.f / s;
    float* dst = dstBase + c;
    dst[(lane)      * 12] = e0 * inv;
    dst[(lane + 32) * 12] = e1 * inv;
    dst[(lane + 64) * 12] = e2 * inv;
    if (lane < 4) dst[(lane + 96) * 12] = e3 * inv;
}

// A softmax for one (g,j,d) -> sTdst[j*72 + c*8 + d]
__device__ __forceinline__ void asoftmax_one(int g, int j, int d,
                                             const float* __restrict__ A,
                                             float* __restrict__ sTdst) {
    float v[8]; float mx = -1e30f;
#pragma unroll
    for (int c = 0; c < 8; ++c) { v[c] = A[c * 128 + d * 16 + j * 4 + g]; mx = fmaxf(mx, v[c]); }
    float s = 0.f;
#pragma unroll
    for (int c = 0; c < 8; ++c) { v[c] = __expf(v[c] - mx); s += v[c]; }
    float inv = 1.f / s;
#pragma unroll
    for (int c = 0; c < 8; ++c) sTdst[j * 72 + c * 8 + d] = v[c] * inv;
}

// ================ single fused kernel ================
__global__ void __launch_bounds__(512) k_all(const int* __restrict__ x,
                                             const float* __restrict__ A,
                                             const float* __restrict__ Bm,
                                             const float* __restrict__ Pi,
                                             float* __restrict__ out) {
    __shared__ __align__(16) float sT[288];          // own g: [j*72 + c*8 + d]
    __shared__ __align__(16) float sB[1200];         // own g: [sym*12 + c]
    __shared__ __align__(16) float pool[7716];       // phase-aliased
    __shared__ unsigned int sLast;

    // pool carving:
    //   phase A : sU  = pool+0    (4800)  [(j*100+v)*12 + d]
    //             sLN = pool+4800 (100)
    //             sB6 = pool+4900 (2560)  [n6l*10 + d], n6l 0..255
    //             sE6 = pool+7460 (256)
    //   phase B : sB4 = pool+0    (160)   [n4l*10 + d], n4l 0..15
    //             sE4 = pool+160  (16)    (sB6/sE6 still live: read-only)
    //   tail    : sT2 = pool+0    (1152)  sB2t = pool+1152 (4800)  sPi = pool+5952 (32)
    float* const sU  = pool;
    float* const sLN = pool + 4800;
    float* const sB6 = pool + 4900;
    float* const sE6 = pool + 7460;
    float* const sB4 = pool;
    float* const sE4 = pool + 160;

    int g   = blockIdx.x >> 7;
    int blk = blockIdx.x & 127;
    int t   = threadIdx.x;
    int w = t >> 5, lane = t & 31;
    int grp = lane >> 3, d = lane & 7;

    // ---- prep: own g tables ----
    if (w < 8) bsoftmax_warp(g, w, lane, Bm, sB);
    if (t < 32) asoftmax_one(g, t >> 3, t & 7, A, sT);
    __syncthreads();

    // ---- leaf-lift table U and LN for own g ----
    if (t < 400) {
        int j = t / 100, v = t - 100 * j;
        float e[8];
#pragma unroll
        for (int c = 0; c < 8; ++c) e[c] = sB[v * 12 + c];
        float s = sum8r(e);
        float inv = 1.f / s;
        float* dst = &sU[(j * 100 + v) * 12];
#pragma unroll
        for (int dd = 0; dd < 8; ++dd) {
            float acc = 0.f;
#pragma unroll
            for (int c = 0; c < 8; ++c) acc = fmaf(sT[j * 72 + c * 8 + dd], e[c], acc);
            dst[dd] = acc * inv;
        }
        if (j == 0) sLN[v] = __logf(s);
    }
    __syncthreads();

    // ---- phase A: levels 8,7,6 ; 8-lane group per n6, 4 iters ----
#pragma unroll 1
    for (int it = 0; it < 4; ++it) {
        int n6l = it * 64 + w * 4 + grp;             // 0..255
        int n6g = (blk << 8) + n6l;

        int v6 = __ldg(&x[OFF6 + n6g]);
        float p6 = sB[v6 * 12 + d];
        float ell = 0.f;

#pragma unroll
        for (int j7 = 0; j7 < 4; ++j7) {
            int v7 = __ldg(&x[OFF7 + 4 * n6g + j7]);
            int4 v8 = *reinterpret_cast<const int4*>(&x[OFF8 + 16 * n6g + 4 * j7]);

            float p  = sB[v7 * 12 + d];
            float u0 = sU[(      v8.x) * 12 + d];
            float u1 = sU[(100 + v8.y) * 12 + d];
            float u2 = sU[(200 + v8.z) * 12 + d];
            float u3 = sU[(300 + v8.w) * 12 + d];
            p *= (u0 * u1) * (u2 * u3);
            ell += (sLN[v8.x] + sLN[v8.y]) + (sLN[v8.z] + sLN[v8.w]);

            float nu = groupSum8(p);
            ell += __logf(nu);
            float pinv = p * __fdividef(1.f, nu);
            p6 *= groupMatvec(&sT[j7 * 72], pinv, d);
        }
        float nu6 = groupSum8(p6);
        ell += __logf(nu6);
        sB6[n6l * 10 + d] = p6 * __fdividef(1.f, nu6);
        if (d == 0) sE6[n6l] = ell;
    }
    __syncthreads();

    // ---- phase B: levels 6->5->4 ; warp per n4 (16 warps) -> sB4 ----
    if (w < 16) {
        int n4l = w;                                 // 0..15
        int n4g = (blk << 4) + n4l;
        int n5g = 4 * n4g + grp;

        float p = sB[__ldg(&x[OFF5 + n5g]) * 12 + d];
        float ell = 0.f;
#pragma unroll
        for (int j6 = 0; j6 < 4; ++j6) {
            int n6l = 16 * n4l + 4 * grp + j6;
            float b = sB6[n6l * 10 + d];
            ell += sE6[n6l];
            p *= groupMatvec(&sT[j6 * 72], b, d);
        }
        float nu = groupSum8(p);
        ell += __logf(nu);
        p *= __fdividef(1.f, nu);

        float m = groupMatvec(&sT[grp * 72], p, d);
        m   *= __shfl_xor_sync(0xffffffffu, m, 8);
        ell += __shfl_xor_sync(0xffffffffu, ell, 8);
        m   *= __shfl_xor_sync(0xffffffffu, m, 16);
        ell += __shfl_xor_sync(0xffffffffu, ell, 16);

        float p4 = sB[__ldg(&x[OFF4 + n4g]) * 12 + d] * m;
        float nu4 = groupSum8(p4);
        ell += __logf(nu4);
        p4 *= __fdividef(1.f, nu4);

        if (grp == 0)  sB4[n4l * 10 + d] = p4;
        if (lane == 0) sE4[n4l] = ell;
    }
    __syncthreads();

    // ---- phase C: levels 4->3->2 ; warp 0 (one n2 per block) -> gmem ----
    if (w == 0) {
        int n2g = blk;                               // 0..127
        int n3g = 4 * n2g + grp;

        float p = sB[__ldg(&x[OFF3 + n3g]) * 12 + d];
        float ell = 0.f;
#pragma unroll
        for (int j4 = 0; j4 < 4; ++j4) {
            int n4l = 4 * grp + j4;
            float b = sB4[n4l * 10 + d];
            ell += sE4[n4l];
            p *= groupMatvec(&sT[j4 * 72], b, d);
        }
        float nu = groupSum8(p);
        ell += __logf(nu);
        p *= __fdividef(1.f, nu);

        float m = groupMatvec(&sT[grp * 72], p, d);
        m   *= __shfl_xor_sync(0xffffffffu, m, 8);
        ell += __shfl_xor_sync(0xffffffffu, ell, 8);
        m   *= __shfl_xor_sync(0xffffffffu, m, 16);
        ell += __shfl_xor_sync(0xffffffffu, ell, 16);

        float p2 = sB[__ldg(&x[OFF2 + n2g]) * 12 + d] * m;
        float nu2 = groupSum8(p2);
        ell += __logf(nu2);
        p2 *= __fdividef(1.f, nu2);

        if (grp == 0)  g_beta2[((size_t)g * N2 + n2g) * 8 + d] = p2;
        if (lane == 0) g_ell2[(size_t)g * N2 + n2g] = ell;
    }
    __syncthreads();

    // ---- arrival: last block does the tail ----
    __threadfence();
    if (t == 0) {
        unsigned int prev = atomicAdd(&g_ctr, 1u);
        sLast = (prev == NBLK - 1) ? 1u : 0u;
    }
    __syncthreads();
    if (!sLast) return;

    // ======== tail (single block): levels 2->1->0 + Pi for all (g,tree) ========
    float* const sT2  = pool;            // 4*288
    float* const sB2t = pool + 1152;     // 4*1200
    float* const sPi  = pool + 5952;     // 4*8

    {
        for (int rep = 0; rep < 2; ++rep) {
            int job = w + 16 * rep;              // 0..31 -> (c = job>>2, g = job&3)
            bsoftmax_warp(job & 3, job >> 2, lane, Bm, sB2t + (job & 3) * 1200);
        }
        if (t < 128) {
            int gg = t >> 5, rem = t & 31;
            asoftmax_one(gg, rem >> 3, rem & 7, A, sT2 + gg * 288);
        } else if (t < 132) {
            int gg = t - 128;
            float v[8]; float mx = -1e30f;
#pragma unroll
            for (int c = 0; c < 8; ++c) { v[c] = Pi[c * 4 + gg]; mx = fmaxf(mx, v[c]); }
            float s = 0.f;
#pragma unroll
            for (int c = 0; c < 8; ++c) { v[c] = __expf(v[c] - mx); s += v[c]; }
            float inv = 1.f / s;
#pragma unroll
            for (int c = 0; c < 8; ++c) sPi[gg * 8 + c] = v[c] * inv;
        }
    }
    __syncthreads();

#pragma unroll 1
    for (int rep = 0; rep < 2; ++rep) {
        int idx = w * 2 + rep;                   // 0..31
        int gg = idx >> 3, tree = idx & 7;
        const float* Bt = sB2t + gg * 1200;
        const float* Tt = sT2 + gg * 288;
        int n1 = 4 * tree + grp;

        float p = Bt[__ldg(&x[OFF1 + n1]) * 12 + d];
        float ell = 0.f;
#pragma unroll
        for (int j2 = 0; j2 < 4; ++j2) {
            int n2 = 4 * n1 + j2;
            float b = __ldcg(&g_beta2[((size_t)gg * N2 + n2) * 8 + d]);
            ell += __ldcg(&g_ell2[(size_t)gg * N2 + n2]);
            p *= groupMatvec(&Tt[j2 * 72], b, d);
        }
        float nu = groupSum8(p);
        ell += __logf(nu);
        p *= __fdividef(1.f, nu);

        float m = groupMatvec(&Tt[grp * 72], p, d);
        m   *= __shfl_xor_sync(0xffffffffu, m, 8);
        ell += __shfl_xor_sync(0xffffffffu, ell, 8);
        m   *= __shfl_xor_sync(0xffffffffu, m, 16);
        ell += __shfl_xor_sync(0xffffffffu, ell, 16);

        float p0 = Bt[__ldg(&x[OFF0 + tree]) * 12 + d] * m;
        float nu0 = groupSum8(p0);
        ell += __logf(nu0);
        p0 *= __fdividef(1.f, nu0);

        float Z = groupSum8(sPi[gg * 8 + d] * p0);
        if (lane == 0) out[tree * NGEN + gg] = __logf(Z) + ell;
    }

    __syncthreads();
    if (t == 0) g_ctr = 0;      // reset for next graph replay
}

// ---------------- launcher ----------------
extern "C" void kernel_launch(void* const* d_in, const int* in_sizes, int n_in,
                              void* d_out, int out_size) {
    const int*   x  = nullptr;
    const float* A  = nullptr;
    const float* Bm = nullptr;
    const float* Pi = nullptr;
    for (int i = 0; i < n_in; ++i) {
        switch (in_sizes[i]) {
            case DIMX: x  = (const int*)  d_in[i]; break;
            case 1024: A  = (const float*)d_in[i]; break;
            case 3200: Bm = (const float*)d_in[i]; break;
            case 32:   Pi = (const float*)d_in[i]; break;
            default: break;
        }
    }
    k_all<<<NBLK, 512>>>(x, A, Bm, Pi, (float*)d_out);
}

// round 8
// speedup vs baseline: 1.3240x; 1.3240x over previous
#include <cuda_runtime.h>

// ---------------- problem constants ----------------
#define NGEN  4
#define NSYM  100
// level offsets into x (cumsum of 8*4^l)
#define OFF0 0
#define OFF1 8
#define OFF2 40
#define OFF3 168
#define OFF4 680
#define OFF5 2728
#define OFF6 10920
#define OFF7 43688
#define OFF8 174760
#define DIMX 699048

#define N2 128
#define NBLK 512     // 4 g x 128

// ---------------- scratch (static device, no allocs) ----------------
__device__ float g_beta2[(size_t)NGEN * N2 * 8];
__device__ float g_ell2 [(size_t)NGEN * N2];
__device__ unsigned int g_ctr = 0;

// ---------------- helpers ----------------
__device__ __forceinline__ void emload(const float* __restrict__ sB, int v, float e[8]) {
    const float4* p = reinterpret_cast<const float4*>(sB + v * 12);
    float4 a = p[0], b = p[1];
    e[0] = a.x; e[1] = a.y; e[2] = a.z; e[3] = a.w;
    e[4] = b.x; e[5] = b.y; e[6] = b.z; e[7] = b.w;
}

// m[d] = sum_c sTj[c*8+d] * r[c]
__device__ __forceinline__ void matvecS(const float* __restrict__ sTj, const float r[8], float m[8]) {
    const float4* T4 = reinterpret_cast<const float4*>(sTj);
#pragma unroll
    for (int c = 0; c < 8; ++c) {
        float4 t0 = T4[2 * c];
        float4 t1 = T4[2 * c + 1];
        float rc = r[c];
        if (c == 0) {
            m[0] = t0.x * rc; m[1] = t0.y * rc; m[2] = t0.z * rc; m[3] = t0.w * rc;
            m[4] = t1.x * rc; m[5] = t1.y * rc; m[6] = t1.z * rc; m[7] = t1.w * rc;
        } else {
            m[0] = fmaf(t0.x, rc, m[0]); m[1] = fmaf(t0.y, rc, m[1]);
            m[2] = fmaf(t0.z, rc, m[2]); m[3] = fmaf(t0.w, rc, m[3]);
            m[4] = fmaf(t1.x, rc, m[4]); m[5] = fmaf(t1.y, rc, m[5]);
            m[6] = fmaf(t1.z, rc, m[6]); m[7] = fmaf(t1.w, rc, m[7]);
        }
    }
}

__device__ __forceinline__ float sum8r(const float v[8]) {
    return ((v[0] + v[1]) + (v[2] + v[3])) + ((v[4] + v[5]) + (v[6] + v[7]));
}

__device__ __forceinline__ float groupSum8(float v) {
    v += __shfl_xor_sync(0xffffffffu, v, 4, 8);
    v += __shfl_xor_sync(0xffffffffu, v, 2, 8);
    v += __shfl_xor_sync(0xffffffffu, v, 1, 8);
    return v;
}

__device__ __forceinline__ float groupMatvec(const float* __restrict__ sTj, float bhat, int d) {
    float m = 0.f;
#pragma unroll
    for (int c = 0; c < 8; ++c) {
        float bc = __shfl_sync(0xffffffffu, bhat, c, 8);
        m = fmaf(sTj[c * 8 + d], bc, m);
    }
    return m;
}

// B softmax for one (g,c) by one warp -> dstBase[sym*12 + c]
__device__ __forceinline__ void bsoftmax_warp(int g, int c, int lane,
                                              const float* __restrict__ Bm,
                                              float* __restrict__ dstBase) {
    const float* src = Bm + c * 400 + g;
    float v0 = src[(lane)      * 4];
    float v1 = src[(lane + 32) * 4];
    float v2 = src[(lane + 64) * 4];
    float v3 = (lane < 4) ? src[(lane + 96) * 4] : -1e30f;
    float mx = fmaxf(fmaxf(v0, v1), fmaxf(v2, v3));
#pragma unroll
    for (int off = 16; off >= 1; off >>= 1)
        mx = fmaxf(mx, __shfl_xor_sync(0xffffffffu, mx, off));
    float e0 = __expf(v0 - mx), e1 = __expf(v1 - mx), e2 = __expf(v2 - mx);
    float e3 = (lane < 4) ? __expf(v3 - mx) : 0.f;
    float s = e0 + e1 + e2 + e3;
#pragma unroll
    for (int off = 16; off >= 1; off >>= 1)
        s += __shfl_xor_sync(0xffffffffu, s, off);
    float inv = 1.f / s;
    float* dst = dstBase + c;
    dst[(lane)      * 12] = e0 * inv;
    dst[(lane + 32) * 12] = e1 * inv;
    dst[(lane + 64) * 12] = e2 * inv;
    if (lane < 4) dst[(lane + 96) * 12] = e3 * inv;
}

// A softmax for one (g,j,d) -> sTdst[j*72 + c*8 + d]
__device__ __forceinline__ void asoftmax_one(int g, int j, int d,
                                             const float* __restrict__ A,
                                             float* __restrict__ sTdst) {
    float v[8]; float mx = -1e30f;
#pragma unroll
    for (int c = 0; c < 8; ++c) { v[c] = A[c * 128 + d * 16 + j * 4 + g]; mx = fmaxf(mx, v[c]); }
    float s = 0.f;
#pragma unroll
    for (int c = 0; c < 8; ++c) { v[c] = __expf(v[c] - mx); s += v[c]; }
    float inv = 1.f / s;
#pragma unroll
    for (int c = 0; c < 8; ++c) sTdst[j * 72 + c * 8 + d] = v[c] * inv;
}

// ================ single fused kernel ================
__global__ void __launch_bounds__(256, 6) k_all(const int* __restrict__ x,
                                                const float* __restrict__ A,
                                                const float* __restrict__ Bm,
                                                const float* __restrict__ Pi,
                                                float* __restrict__ out) {
    __shared__ __align__(16) float sT[288];          // own g: [j*72 + c*8 + d]
    __shared__ __align__(16) float sB[1200];         // own g: [sym*12 + c]
    __shared__ __align__(16) float pool[7716];       // phase-aliased
    __shared__ unsigned int sLast;

    // pool carving:
    //   phase A : sU  = pool+0    (4800)  [(j*100+v)*12 + d]
    //             sLN = pool+4800 (100)
    //             sB6 = pool+4900 (2560)  [n6l*10 + d], n6l 0..255
    //             sE6 = pool+7460 (256)
    //   phase B : sB4 = pool+0    (160)   sE4 = pool+160 (16)  (sB6/sE6 read-only)
    //   tail    : sT2 = pool+0    (1152)  sB2t = pool+1152 (4800)  sPi = pool+5952 (32)
    float* const sU  = pool;
    float* const sLN = pool + 4800;
    float* const sB6 = pool + 4900;
    float* const sE6 = pool + 7460;
    float* const sB4 = pool;
    float* const sE4 = pool + 160;

    int g   = blockIdx.x >> 7;
    int blk = blockIdx.x & 127;
    int t   = threadIdx.x;
    int w = t >> 5, lane = t & 31;
    int grp = lane >> 3, d = lane & 7;

    // ---- prep: own g tables ----
    if (w < 8) bsoftmax_warp(g, w, lane, Bm, sB);
    if (t < 32) asoftmax_one(g, t >> 3, t & 7, A, sT);
    __syncthreads();

    // ---- leaf-lift table U and LN for own g ----
    for (int job = t; job < 400; job += 256) {
        int j = job / 100, v = job - 100 * j;
        float e[8];
#pragma unroll
        for (int c = 0; c < 8; ++c) e[c] = sB[v * 12 + c];
        float s = sum8r(e);
        float inv = 1.f / s;
        float* dst = &sU[(j * 100 + v) * 12];
#pragma unroll
        for (int dd = 0; dd < 8; ++dd) {
            float acc = 0.f;
#pragma unroll
            for (int c = 0; c < 8; ++c) acc = fmaf(sT[j * 72 + c * 8 + dd], e[c], acc);
            dst[dd] = acc * inv;
        }
        if (j == 0) sLN[v] = __logf(s);
    }
    __syncthreads();

    // ---- phase A: levels 8,7,6 ; thread per n6 (256 per block) ----
    {
        int n6 = (blk << 8) + t;
        float p6[8]; emload(sB, __ldg(&x[OFF6 + n6]), p6);
        float ell = 0.f;
#pragma unroll 1
        for (int j7 = 0; j7 < 4; ++j7) {
            int v7  = __ldg(&x[OFF7 + 4 * n6 + j7]);
            int4 v8 = *reinterpret_cast<const int4*>(&x[OFF8 + 16 * n6 + 4 * j7]);

            float p[8]; emload(sB, v7, p);
            {
                const float4* u0 = reinterpret_cast<const float4*>(sU + (      v8.x) * 12);
                const float4* u1 = reinterpret_cast<const float4*>(sU + (100 + v8.y) * 12);
                const float4* u2 = reinterpret_cast<const float4*>(sU + (200 + v8.z) * 12);
                const float4* u3 = reinterpret_cast<const float4*>(sU + (300 + v8.w) * 12);
                float4 a0 = u0[0], b0 = u0[1], a1 = u1[0], b1 = u1[1];
                float4 a2 = u2[0], b2 = u2[1], a3 = u3[0], b3 = u3[1];
                p[0] *= (a0.x * a1.x) * (a2.x * a3.x);
                p[1] *= (a0.y * a1.y) * (a2.y * a3.y);
                p[2] *= (a0.z * a1.z) * (a2.z * a3.z);
                p[3] *= (a0.w * a1.w) * (a2.w * a3.w);
                p[4] *= (b0.x * b1.x) * (b2.x * b3.x);
                p[5] *= (b0.y * b1.y) * (b2.y * b3.y);
                p[6] *= (b0.z * b1.z) * (b2.z * b3.z);
                p[7] *= (b0.w * b1.w) * (b2.w * b3.w);
                ell += (sLN[v8.x] + sLN[v8.y]) + (sLN[v8.z] + sLN[v8.w]);
            }
            float nu  = sum8r(p);
            ell      += __logf(nu);
            float inv = __fdividef(1.f, nu);
            float m[8]; matvecS(&sT[j7 * 72], p, m);
#pragma unroll
            for (int dd = 0; dd < 8; ++dd) p6[dd] *= m[dd] * inv;
        }
        float nu6  = sum8r(p6);
        ell       += __logf(nu6);
        float inv6 = __fdividef(1.f, nu6);
#pragma unroll
        for (int dd = 0; dd < 8; ++dd) sB6[t * 10 + dd] = p6[dd] * inv6;
        sE6[t] = ell;
    }
    __syncthreads();

    // ---- phase B: levels 6->5->4 ; warp per n4 (8 warps x 2) -> sB4 ----
    {
#pragma unroll 1
        for (int i = 0; i < 2; ++i) {
            int n4l = w * 2 + i;                 // 0..15
            int n4g = (blk << 4) + n4l;
            int n5g = 4 * n4g + grp;

            float p = sB[__ldg(&x[OFF5 + n5g]) * 12 + d];
            float ell = 0.f;
#pragma unroll
            for (int j6 = 0; j6 < 4; ++j6) {
                int n6l = 16 * n4l + 4 * grp + j6;
                float b = sB6[n6l * 10 + d];
                ell += sE6[n6l];
                p *= groupMatvec(&sT[j6 * 72], b, d);
            }
            float nu = groupSum8(p);
            ell += __logf(nu);
            p *= __fdividef(1.f, nu);

            float m = groupMatvec(&sT[grp * 72], p, d);
            m   *= __shfl_xor_sync(0xffffffffu, m, 8);
            ell += __shfl_xor_sync(0xffffffffu, ell, 8);
            m   *= __shfl_xor_sync(0xffffffffu, m, 16);
            ell += __shfl_xor_sync(0xffffffffu, ell, 16);

            float p4 = sB[__ldg(&x[OFF4 + n4g]) * 12 + d] * m;
            float nu4 = groupSum8(p4);
            ell += __logf(nu4);
            p4 *= __fdividef(1.f, nu4);

            if (grp == 0)  sB4[n4l * 10 + d] = p4;
            if (lane == 0) sE4[n4l] = ell;
        }
    }
    __syncthreads();

    // ---- phase C: levels 4->3->2 ; warp 0 -> gmem ----
    if (w == 0) {
        int n2g = blk;                               // 0..127
        int n3g = 4 * n2g + grp;

        float p = sB[__ldg(&x[OFF3 + n3g]) * 12 + d];
        float ell = 0.f;
#pragma unroll
        for (int j4 = 0; j4 < 4; ++j4) {
            int n4l = 4 * grp + j4;
            float b = sB4[n4l * 10 + d];
            ell += sE4[n4l];
            p *= groupMatvec(&sT[j4 * 72], b, d);
        }
        float nu = groupSum8(p);
        ell += __logf(nu);
        p *= __fdividef(1.f, nu);

        float m = groupMatvec(&sT[grp * 72], p, d);
        m   *= __shfl_xor_sync(0xffffffffu, m, 8);
        ell += __shfl_xor_sync(0xffffffffu, ell, 8);
        m   *= __shfl_xor_sync(0xffffffffu, m, 16);
        ell += __shfl_xor_sync(0xffffffffu, ell, 16);

        float p2 = sB[__ldg(&x[OFF2 + n2g]) * 12 + d] * m;
        float nu2 = groupSum8(p2);
        ell += __logf(nu2);
        p2 *= __fdividef(1.f, nu2);

        if (grp == 0)  g_beta2[((size_t)g * N2 + n2g) * 8 + d] = p2;
        if (lane == 0) g_ell2[(size_t)g * N2 + n2g] = ell;
    }
    __syncthreads();

    // ---- arrival: last block does the tail ----
    __threadfence();
    if (t == 0) {
        unsigned int prev = atomicAdd(&g_ctr, 1u);
        sLast = (prev == NBLK - 1) ? 1u : 0u;
    }
    __syncthreads();
    if (!sLast) return;

    // ======== tail (single block): levels 2->1->0 + Pi for all (g,tree) ========
    float* const sT2  = pool;            // 4*288
    float* const sB2t = pool + 1152;     // 4*1200
    float* const sPi  = pool + 5952;     // 4*8

    {
        for (int rep = 0; rep < 4; ++rep) {
            int job = w + 8 * rep;               // 0..31 -> (c = job>>2, g = job&3)
            bsoftmax_warp(job & 3, job >> 2, lane, Bm, sB2t + (job & 3) * 1200);
        }
        if (t < 128) {
            int gg = t >> 5, rem = t & 31;
            asoftmax_one(gg, rem >> 3, rem & 7, A, sT2 + gg * 288);
        } else if (t < 132) {
            int gg = t - 128;
            float v[8]; float mx = -1e30f;
#pragma unroll
            for (int c = 0; c < 8; ++c) { v[c] = Pi[c * 4 + gg]; mx = fmaxf(mx, v[c]); }
            float s = 0.f;
#pragma unroll
            for (int c = 0; c < 8; ++c) { v[c] = __expf(v[c] - mx); s += v[c]; }
            float inv = 1.f / s;
#pragma unroll
            for (int c = 0; c < 8; ++c) sPi[gg * 8 + c] = v[c] * inv;
        }
    }
    __syncthreads();

#pragma unroll 1
    for (int rep = 0; rep < 4; ++rep) {
        int idx = w * 4 + rep;                   // 0..31
        int gg = idx >> 3, tree = idx & 7;
        const float* Bt = sB2t + gg * 1200;
        const float* Tt = sT2 + gg * 288;
        int n1 = 4 * tree + grp;

        float p = Bt[__ldg(&x[OFF1 + n1]) * 12 + d];
        float ell = 0.f;
#pragma unroll
        for (int j2 = 0; j2 < 4; ++j2) {
            int n2 = 4 * n1 + j2;
            float b = __ldcg(&g_beta2[((size_t)gg * N2 + n2) * 8 + d]);
            ell += __ldcg(&g_ell2[(size_t)gg * N2 + n2]);
            p *= groupMatvec(&Tt[j2 * 72], b, d);
        }
        float nu = groupSum8(p);
        ell += __logf(nu);
        p *= __fdividef(1.f, nu);

        float m = groupMatvec(&Tt[grp * 72], p, d);
        m   *= __shfl_xor_sync(0xffffffffu, m, 8);
        ell += __shfl_xor_sync(0xffffffffu, ell, 8);
        m   *= __shfl_xor_sync(0xffffffffu, m, 16);
        ell += __shfl_xor_sync(0xffffffffu, ell, 16);

        float p0 = Bt[__ldg(&x[OFF0 + tree]) * 12 + d] * m;
        float nu0 = groupSum8(p0);
        ell += __logf(nu0);
        p0 *= __fdividef(1.f, nu0);

        float Z = groupSum8(sPi[gg * 8 + d] * p0);
        if (lane == 0) out[tree * NGEN + gg] = __logf(Z) + ell;
    }

    __syncthreads();
    if (t == 0) g_ctr = 0;      // reset for next graph replay
}

// ---------------- launcher ----------------
extern "C" void kernel_launch(void* const* d_in, const int* in_sizes, int n_in,
                              void* d_out, int out_size) {
    const int*   x  = nullptr;
    const float* A  = nullptr;
    const float* Bm = nullptr;
    const float* Pi = nullptr;
    for (int i = 0; i < n_in; ++i) {
        switch (in_sizes[i]) {
            case DIMX: x  = (const int*)  d_in[i]; break;
            case 1024: A  = (const float*)d_in[i]; break;
            case 3200: Bm = (const float*)d_in[i]; break;
            case 32:   Pi = (const float*)d_in[i]; break;
            default: break;
        }
    }
    k_all<<<NBLK, 256>>>(x, A, Bm, Pi, (float*)d_out);
}

// round 9
// speedup vs baseline: 1.3859x; 1.0467x over previous
#include <cuda_runtime.h>

// ---------------- problem constants ----------------
#define NGEN  4
#define NSYM  100
// level offsets into x (cumsum of 8*4^l)
#define OFF0 0
#define OFF1 8
#define OFF2 40
#define OFF3 168
#define OFF4 680
#define OFF5 2728
#define OFF6 10920
#define OFF7 43688
#define OFF8 174760
#define DIMX 699048

#define N2 128
#define NBLK 512     // 4 g x 128

// ---------------- scratch (static device, no allocs) ----------------
__device__ float g_beta2[(size_t)NGEN * N2 * 8];
__device__ float g_ell2 [(size_t)NGEN * N2];
__device__ unsigned int g_ctr = 0;

// ---------------- helpers ----------------
__device__ __forceinline__ void emload(const float* __restrict__ sB, int v, float e[8]) {
    const float4* p = reinterpret_cast<const float4*>(sB + v * 12);
    float4 a = p[0], b = p[1];
    e[0] = a.x; e[1] = a.y; e[2] = a.z; e[3] = a.w;
    e[4] = b.x; e[5] = b.y; e[6] = b.z; e[7] = b.w;
}

// p[d] = em7[d] * prod_j8 U[j8][v8_j8][d]   (U unnormalized)
__device__ __forceinline__ void leafprod(const float* __restrict__ sB,
                                         const float* __restrict__ sU,
                                         int v7, int4 v8, float p[8]) {
    const float4* e  = reinterpret_cast<const float4*>(sB + v7 * 12);
    const float4* u0 = reinterpret_cast<const float4*>(sU + (      v8.x) * 12);
    const float4* u1 = reinterpret_cast<const float4*>(sU + (100 + v8.y) * 12);
    const float4* u2 = reinterpret_cast<const float4*>(sU + (200 + v8.z) * 12);
    const float4* u3 = reinterpret_cast<const float4*>(sU + (300 + v8.w) * 12);
    float4 ea = e[0],  eb = e[1];
    float4 a0 = u0[0], b0 = u0[1];
    float4 a1 = u1[0], b1 = u1[1];
    float4 a2 = u2[0], b2 = u2[1];
    float4 a3 = u3[0], b3 = u3[1];
    p[0] = ea.x * ((a0.x * a1.x) * (a2.x * a3.x));
    p[1] = ea.y * ((a0.y * a1.y) * (a2.y * a3.y));
    p[2] = ea.z * ((a0.z * a1.z) * (a2.z * a3.z));
    p[3] = ea.w * ((a0.w * a1.w) * (a2.w * a3.w));
    p[4] = eb.x * ((b0.x * b1.x) * (b2.x * b3.x));
    p[5] = eb.y * ((b0.y * b1.y) * (b2.y * b3.y));
    p[6] = eb.z * ((b0.z * b1.z) * (b2.z * b3.z));
    p[7] = eb.w * ((b0.w * b1.w) * (b2.w * b3.w));
}

// m[d] = sum_c sTj[c*8+d] * r[c]
__device__ __forceinline__ void matvecS(const float* __restrict__ sTj, const float r[8], float m[8]) {
    const float4* T4 = reinterpret_cast<const float4*>(sTj);
#pragma unroll
    for (int c = 0; c < 8; ++c) {
        float4 t0 = T4[2 * c];
        float4 t1 = T4[2 * c + 1];
        float rc = r[c];
        if (c == 0) {
            m[0] = t0.x * rc; m[1] = t0.y * rc; m[2] = t0.z * rc; m[3] = t0.w * rc;
            m[4] = t1.x * rc; m[5] = t1.y * rc; m[6] = t1.z * rc; m[7] = t1.w * rc;
        } else {
            m[0] = fmaf(t0.x, rc, m[0]); m[1] = fmaf(t0.y, rc, m[1]);
            m[2] = fmaf(t0.z, rc, m[2]); m[3] = fmaf(t0.w, rc, m[3]);
            m[4] = fmaf(t1.x, rc, m[4]); m[5] = fmaf(t1.y, rc, m[5]);
            m[6] = fmaf(t1.z, rc, m[6]); m[7] = fmaf(t1.w, rc, m[7]);
        }
    }
}

__device__ __forceinline__ float sum8r(const float v[8]) {
    return ((v[0] + v[1]) + (v[2] + v[3])) + ((v[4] + v[5]) + (v[6] + v[7]));
}

__device__ __forceinline__ float groupSum8(float v) {
    v += __shfl_xor_sync(0xffffffffu, v, 4, 8);
    v += __shfl_xor_sync(0xffffffffu, v, 2, 8);
    v += __shfl_xor_sync(0xffffffffu, v, 1, 8);
    return v;
}

__device__ __forceinline__ float groupMatvec(const float* __restrict__ sTj, float bhat, int d) {
    float m = 0.f;
#pragma unroll
    for (int c = 0; c < 8; ++c) {
        float bc = __shfl_sync(0xffffffffu, bhat, c, 8);
        m = fmaf(sTj[c * 8 + d], bc, m);
    }
    return m;
}

// B softmax for one (g,c) by one warp -> dstBase[sym*12 + c]
__device__ __forceinline__ void bsoftmax_warp(int g, int c, int lane,
                                              const float* __restrict__ Bm,
                                              float* __restrict__ dstBase) {
    const float* src = Bm + c * 400 + g;
    float v0 = src[(lane)      * 4];
    float v1 = src[(lane + 32) * 4];
    float v2 = src[(lane + 64) * 4];
    float v3 = (lane < 4) ? src[(lane + 96) * 4] : -1e30f;
    float mx = fmaxf(fmaxf(v0, v1), fmaxf(v2, v3));
#pragma unroll
    for (int off = 16; off >= 1; off >>= 1)
        mx = fmaxf(mx, __shfl_xor_sync(0xffffffffu, mx, off));
    float e0 = __expf(v0 - mx), e1 = __expf(v1 - mx), e2 = __expf(v2 - mx);
    float e3 = (lane < 4) ? __expf(v3 - mx) : 0.f;
    float s = e0 + e1 + e2 + e3;
#pragma unroll
    for (int off = 16; off >= 1; off >>= 1)
        s += __shfl_xor_sync(0xffffffffu, s, off);
    float inv = 1.f / s;
    float* dst = dstBase + c;
    dst[(lane)      * 12] = e0 * inv;
    dst[(lane + 32) * 12] = e1 * inv;
    dst[(lane + 64) * 12] = e2 * inv;
    if (lane < 4) dst[(lane + 96) * 12] = e3 * inv;
}

// A softmax for one (g,j,d) -> sTdst[j*72 + c*8 + d]
__device__ __forceinline__ void asoftmax_one(int g, int j, int d,
                                             const float* __restrict__ A,
                                             float* __restrict__ sTdst) {
    float v[8]; float mx = -1e30f;
#pragma unroll
    for (int c = 0; c < 8; ++c) { v[c] = A[c * 128 + d * 16 + j * 4 + g]; mx = fmaxf(mx, v[c]); }
    float s = 0.f;
#pragma unroll
    for (int c = 0; c < 8; ++c) { v[c] = __expf(v[c] - mx); s += v[c]; }
    float inv = 1.f / s;
#pragma unroll
    for (int c = 0; c < 8; ++c) sTdst[j * 72 + c * 8 + d] = v[c] * inv;
}

// ================ single fused kernel ================
__global__ void __launch_bounds__(256, 3) k_all(const int* __restrict__ x,
                                                const float* __restrict__ A,
                                                const float* __restrict__ Bm,
                                                const float* __restrict__ Pi,
                                                float* __restrict__ out) {
    __shared__ __align__(16) float sT[288];          // own g: [j*72 + c*8 + d]
    __shared__ __align__(16) float sB[1200];         // own g: [sym*12 + c]
    __shared__ __align__(16) float pool[7616];       // phase-aliased
    __shared__ unsigned int sLast;

    // pool carving:
    //   phase A : sU  = pool+0    (4800)  [(j*100+v)*12 + d]  UNNORMALIZED
    //             sB6 = pool+4800 (2560)  [n6l*10 + d], n6l 0..255
    //             sE6 = pool+7360 (256)
    //   phase B : sB4 = pool+0 (160)  sE4 = pool+160 (16)  (sB6/sE6 read-only)
    //   tail    : sT2 = pool+0 (1152)  sB2t = pool+1152 (4800)  sPi = pool+5952 (32)
    float* const sU  = pool;
    float* const sB6 = pool + 4800;
    float* const sE6 = pool + 7360;
    float* const sB4 = pool;
    float* const sE4 = pool + 160;

    int g   = blockIdx.x >> 7;
    int blk = blockIdx.x & 127;
    int t   = threadIdx.x;
    int w = t >> 5, lane = t & 31;
    int grp = lane >> 3, d = lane & 7;

    // ---- prep: own g tables ----
    if (w < 8) bsoftmax_warp(g, w, lane, Bm, sB);
    if (t < 32) asoftmax_one(g, t >> 3, t & 7, A, sT);
    __syncthreads();

    // ---- leaf-lift table U (unnormalized) for own g ----
    for (int job = t; job < 400; job += 256) {
        int j = job / 100, v = job - 100 * j;
        float e[8];
#pragma unroll
        for (int c = 0; c < 8; ++c) e[c] = sB[v * 12 + c];
        float* dst = &sU[(j * 100 + v) * 12];
#pragma unroll
        for (int dd = 0; dd < 8; ++dd) {
            float acc = 0.f;
#pragma unroll
            for (int c = 0; c < 8; ++c) acc = fmaf(sT[j * 72 + c * 8 + dd], e[c], acc);
            dst[dd] = acc;
        }
    }
    __syncthreads();

    // ---- phase A: levels 8,7,6 ; thread per n6 (256 per block) ----
    {
        int n6 = (blk << 8) + t;
        // batched upfront loads (MLP=6)
        int v6 = __ldg(&x[OFF6 + n6]);
        int4 x7 = *reinterpret_cast<const int4*>(&x[OFF7 + 4 * n6]);
        const int4* px8 = reinterpret_cast<const int4*>(&x[OFF8 + 16 * n6]);
        int4 w0 = px8[0], w1 = px8[1], w2 = px8[2], w3 = px8[3];

        float p6[8]; emload(sB, v6, p6);
        float ell = 0.f;

        // two pairs of independent j7 chains (2-way ILP)
#pragma unroll
        for (int jp = 0; jp < 2; ++jp) {
            int j7a = 2 * jp, j7b = 2 * jp + 1;
            int v7a = (jp == 0) ? x7.x : x7.z;
            int v7b = (jp == 0) ? x7.y : x7.w;
            int4 v8a = (jp == 0) ? w0 : w2;
            int4 v8b = (jp == 0) ? w1 : w3;

            float pA[8], pB[8];
            leafprod(sB, sU, v7a, v8a, pA);
            leafprod(sB, sU, v7b, v8b, pB);

            float nuA = sum8r(pA);
            float nuB = sum8r(pB);
            ell += __logf(nuA) + __logf(nuB);
            float invA = __fdividef(1.f, nuA);
            float invB = __fdividef(1.f, nuB);

            float mA[8]; matvecS(&sT[j7a * 72], pA, mA);
            float mB[8]; matvecS(&sT[j7b * 72], pB, mB);
#pragma unroll
            for (int dd = 0; dd < 8; ++dd)
                p6[dd] *= (mA[dd] * invA) * (mB[dd] * invB);
        }
        float nu6  = sum8r(p6);
        ell       += __logf(nu6);
        float inv6 = __fdividef(1.f, nu6);
#pragma unroll
        for (int dd = 0; dd < 8; ++dd) sB6[t * 10 + dd] = p6[dd] * inv6;
        sE6[t] = ell;
    }
    __syncthreads();

    // ---- phase B: levels 6->5->4 ; warp per n4 (8 warps x 2) -> sB4 ----
    {
#pragma unroll 1
        for (int i = 0; i < 2; ++i) {
            int n4l = w * 2 + i;                 // 0..15
            int n4g = (blk << 4) + n4l;
            int n5g = 4 * n4g + grp;

            float p = sB[__ldg(&x[OFF5 + n5g]) * 12 + d];
            float ell = 0.f;
#pragma unroll
            for (int j6 = 0; j6 < 4; ++j6) {
                int n6l = 16 * n4l + 4 * grp + j6;
                float b = sB6[n6l * 10 + d];
                ell += sE6[n6l];
                p *= groupMatvec(&sT[j6 * 72], b, d);
            }
            float nu = groupSum8(p);
            ell += __logf(nu);
            p *= __fdividef(1.f, nu);

            float m = groupMatvec(&sT[grp * 72], p, d);
            m   *= __shfl_xor_sync(0xffffffffu, m, 8);
            ell += __shfl_xor_sync(0xffffffffu, ell, 8);
            m   *= __shfl_xor_sync(0xffffffffu, m, 16);
            ell += __shfl_xor_sync(0xffffffffu, ell, 16);

            float p4 = sB[__ldg(&x[OFF4 + n4g]) * 12 + d] * m;
            float nu4 = groupSum8(p4);
            ell += __logf(nu4);
            p4 *= __fdividef(1.f, nu4);

            if (grp == 0)  sB4[n4l * 10 + d] = p4;
            if (lane == 0) sE4[n4l] = ell;
        }
    }
    __syncthreads();

    // ---- phase C: levels 4->3->2 ; warp 0 -> gmem ----
    if (w == 0) {
        int n2g = blk;                               // 0..127
        int n3g = 4 * n2g + grp;

        float p = sB[__ldg(&x[OFF3 + n3g]) * 12 + d];
        float ell = 0.f;
#pragma unroll
        for (int j4 = 0; j4 < 4; ++j4) {
            int n4l = 4 * grp + j4;
            float b = sB4[n4l * 10 + d];
            ell += sE4[n4l];
            p *= groupMatvec(&sT[j4 * 72], b, d);
        }
        float nu = groupSum8(p);
        ell += __logf(nu);
        p *= __fdividef(1.f, nu);

        float m = groupMatvec(&sT[grp * 72], p, d);
        m   *= __shfl_xor_sync(0xffffffffu, m, 8);
        ell += __shfl_xor_sync(0xffffffffu, ell, 8);
        m   *= __shfl_xor_sync(0xffffffffu, m, 16);
        ell += __shfl_xor_sync(0xffffffffu, ell, 16);

        float p2 = sB[__ldg(&x[OFF2 + n2g]) * 12 + d] * m;
        float nu2 = groupSum8(p2);
        ell += __logf(nu2);
        p2 *= __fdividef(1.f, nu2);

        if (grp == 0)  g_beta2[((size_t)g * N2 + n2g) * 8 + d] = p2;
        if (lane == 0) g_ell2[(size_t)g * N2 + n2g] = ell;
    }
    __syncthreads();

    // ---- arrival: last block does the tail ----
    __threadfence();
    if (t == 0) {
        unsigned int prev = atomicAdd(&g_ctr, 1u);
        sLast = (prev == NBLK - 1) ? 1u : 0u;
    }
    __syncthreads();
    if (!sLast) return;

    // ======== tail (single block): levels 2->1->0 + Pi for all (g,tree) ========
    float* const sT2  = pool;            // 4*288
    float* const sB2t = pool + 1152;     // 4*1200
    float* const sPi  = pool + 5952;     // 4*8

    {
        for (int rep = 0; rep < 4; ++rep) {
            int job = w + 8 * rep;               // 0..31 -> (c = job>>2, g = job&3)
            bsoftmax_warp(job & 3, job >> 2, lane, Bm, sB2t + (job & 3) * 1200);
        }
        if (t < 128) {
            int gg = t >> 5, rem = t & 31;
            asoftmax_one(gg, rem >> 3, rem & 7, A, sT2 + gg * 288);
        } else if (t < 132) {
            int gg = t - 128;
            float v[8]; float mx = -1e30f;
#pragma unroll
            for (int c = 0; c < 8; ++c) { v[c] = Pi[c * 4 + gg]; mx = fmaxf(mx, v[c]); }
            float s = 0.f;
#pragma unroll
            for (int c = 0; c < 8; ++c) { v[c] = __expf(v[c] - mx); s += v[c]; }
            float inv = 1.f / s;
#pragma unroll
            for (int c = 0; c < 8; ++c) sPi[gg * 8 + c] = v[c] * inv;
        }
    }
    __syncthreads();

#pragma unroll 1
    for (int rep = 0; rep < 4; ++rep) {
        int idx = w * 4 + rep;                   // 0..31
        int gg = idx >> 3, tree = idx & 7;
        const float* Bt = sB2t + gg * 1200;
        const float* Tt = sT2 + gg * 288;
        int n1 = 4 * tree + grp;

        float p = Bt[__ldg(&x[OFF1 + n1]) * 12 + d];
        float ell = 0.f;
#pragma unroll
        for (int j2 = 0; j2 < 4; ++j2) {
            int n2 = 4 * n1 + j2;
            float b = __ldcg(&g_beta2[((size_t)gg * N2 + n2) * 8 + d]);
            ell += __ldcg(&g_ell2[(size_t)gg * N2 + n2]);
            p *= groupMatvec(&Tt[j2 * 72], b, d);
        }
        float nu = groupSum8(p);
        ell += __logf(nu);
        p *= __fdividef(1.f, nu);

        float m = groupMatvec(&Tt[grp * 72], p, d);
        m   *= __shfl_xor_sync(0xffffffffu, m, 8);
        ell += __shfl_xor_sync(0xffffffffu, ell, 8);
        m   *= __shfl_xor_sync(0xffffffffu, m, 16);
        ell += __shfl_xor_sync(0xffffffffu, ell, 16);

        float p0 = Bt[__ldg(&x[OFF0 + tree]) * 12 + d] * m;
        float nu0 = groupSum8(p0);
        ell += __logf(nu0);
        p0 *= __fdividef(1.f, nu0);

        float Z = groupSum8(sPi[gg * 8 + d] * p0);
        if (lane == 0) out[tree * NGEN + gg] = __logf(Z) + ell;
    }

    __syncthreads();
    if (t == 0) g_ctr = 0;      // reset for next graph replay
}

// ---------------- launcher ----------------
extern "C" void kernel_launch(void* const* d_in, const int* in_sizes, int n_in,
                              void* d_out, int out_size) {
    const int*   x  = nullptr;
    const float* A  = nullptr;
    const float* Bm = nullptr;
    const float* Pi = nullptr;
    for (int i = 0; i < n_in; ++i) {
        switch (in_sizes[i]) {
            case DIMX: x  = (const int*)  d_in[i]; break;
            case 1024: A  = (const float*)d_in[i]; break;
            case 3200: Bm = (const float*)d_in[i]; break;
            case 32:   Pi = (const float*)d_in[i]; break;
            default: break;
        }
    }
    k_all<<<NBLK, 256>>>(x, A, Bm, Pi, (float*)d_out);
}

// round 10
// speedup vs baseline: 1.3874x; 1.0011x over previous
#include <cuda_runtime.h>

// ---------------- problem constants ----------------
#define NGEN  4
#define NSYM  100
// level offsets into x (cumsum of 8*4^l)
#define OFF0 0
#define OFF1 8
#define OFF2 40
#define OFF3 168
#define OFF4 680
#define OFF5 2728
#define OFF6 10920
#define OFF7 43688
#define OFF8 174760
#define DIMX 699048

#define N2 128
#define NBLK 512     // 4 g x 128

// ---------------- scratch (static device, no allocs) ----------------
__device__ float g_beta2[(size_t)NGEN * N2 * 8];
__device__ float g_ell2 [(size_t)NGEN * N2];
__device__ unsigned int g_ctr = 0;

// ---------------- helpers ----------------
__device__ __forceinline__ void emload(const float* __restrict__ sB, int v, float e[8]) {
    const float4* p = reinterpret_cast<const float4*>(sB + v * 12);
    float4 a = p[0], b = p[1];
    e[0] = a.x; e[1] = a.y; e[2] = a.z; e[3] = a.w;
    e[4] = b.x; e[5] = b.y; e[6] = b.z; e[7] = b.w;
}

// p[d] = em7[d] * prod_j8 U[j8][v8_j8][d]   (U unnormalized)
__device__ __forceinline__ void leafprod(const float* __restrict__ sB,
                                         const float* __restrict__ sU,
                                         int v7, int4 v8, float p[8]) {
    const float4* e  = reinterpret_cast<const float4*>(sB + v7 * 12);
    const float4* u0 = reinterpret_cast<const float4*>(sU + (      v8.x) * 12);
    const float4* u1 = reinterpret_cast<const float4*>(sU + (100 + v8.y) * 12);
    const float4* u2 = reinterpret_cast<const float4*>(sU + (200 + v8.z) * 12);
    const float4* u3 = reinterpret_cast<const float4*>(sU + (300 + v8.w) * 12);
    float4 ea = e[0],  eb = e[1];
    float4 a0 = u0[0], b0 = u0[1];
    float4 a1 = u1[0], b1 = u1[1];
    float4 a2 = u2[0], b2 = u2[1];
    float4 a3 = u3[0], b3 = u3[1];
    p[0] = ea.x * ((a0.x * a1.x) * (a2.x * a3.x));
    p[1] = ea.y * ((a0.y * a1.y) * (a2.y * a3.y));
    p[2] = ea.z * ((a0.z * a1.z) * (a2.z * a3.z));
    p[3] = ea.w * ((a0.w * a1.w) * (a2.w * a3.w));
    p[4] = eb.x * ((b0.x * b1.x) * (b2.x * b3.x));
    p[5] = eb.y * ((b0.y * b1.y) * (b2.y * b3.y));
    p[6] = eb.z * ((b0.z * b1.z) * (b2.z * b3.z));
    p[7] = eb.w * ((b0.w * b1.w) * (b2.w * b3.w));
}

// m[d] = sum_c sTj[c*8+d] * r[c]
__device__ __forceinline__ void matvecS(const float* __restrict__ sTj, const float r[8], float m[8]) {
    const float4* T4 = reinterpret_cast<const float4*>(sTj);
#pragma unroll
    for (int c = 0; c < 8; ++c) {
        float4 t0 = T4[2 * c];
        float4 t1 = T4[2 * c + 1];
        float rc = r[c];
        if (c == 0) {
            m[0] = t0.x * rc; m[1] = t0.y * rc; m[2] = t0.z * rc; m[3] = t0.w * rc;
            m[4] = t1.x * rc; m[5] = t1.y * rc; m[6] = t1.z * rc; m[7] = t1.w * rc;
        } else {
            m[0] = fmaf(t0.x, rc, m[0]); m[1] = fmaf(t0.y, rc, m[1]);
            m[2] = fmaf(t0.z, rc, m[2]); m[3] = fmaf(t0.w, rc, m[3]);
            m[4] = fmaf(t1.x, rc, m[4]); m[5] = fmaf(t1.y, rc, m[5]);
            m[6] = fmaf(t1.z, rc, m[6]); m[7] = fmaf(t1.w, rc, m[7]);
        }
    }
}

__device__ __forceinline__ float sum8r(const float v[8]) {
    return ((v[0] + v[1]) + (v[2] + v[3])) + ((v[4] + v[5]) + (v[6] + v[7]));
}

__device__ __forceinline__ float groupSum8(float v) {
    v += __shfl_xor_sync(0xffffffffu, v, 4, 8);
    v += __shfl_xor_sync(0xffffffffu, v, 2, 8);
    v += __shfl_xor_sync(0xffffffffu, v, 1, 8);
    return v;
}

__device__ __forceinline__ float groupMatvec(const float* __restrict__ sTj, float bhat, int d) {
    float m = 0.f;
#pragma unroll
    for (int c = 0; c < 8; ++c) {
        float bc = __shfl_sync(0xffffffffu, bhat, c, 8);
        m = fmaf(sTj[c * 8 + d], bc, m);
    }
    return m;
}

// B softmax for one (g,c) by one warp -> dstBase[sym*12 + c]
__device__ __forceinline__ void bsoftmax_warp(int g, int c, int lane,
                                              const float* __restrict__ Bm,
                                              float* __restrict__ dstBase) {
    const float* src = Bm + c * 400 + g;
    float v0 = src[(lane)      * 4];
    float v1 = src[(lane + 32) * 4];
    float v2 = src[(lane + 64) * 4];
    float v3 = (lane < 4) ? src[(lane + 96) * 4] : -1e30f;
    float mx = fmaxf(fmaxf(v0, v1), fmaxf(v2, v3));
#pragma unroll
    for (int off = 16; off >= 1; off >>= 1)
        mx = fmaxf(mx, __shfl_xor_sync(0xffffffffu, mx, off));
    float e0 = __expf(v0 - mx), e1 = __expf(v1 - mx), e2 = __expf(v2 - mx);
    float e3 = (lane < 4) ? __expf(v3 - mx) : 0.f;
    float s = e0 + e1 + e2 + e3;
#pragma unroll
    for (int off = 16; off >= 1; off >>= 1)
        s += __shfl_xor_sync(0xffffffffu, s, off);
    float inv = 1.f / s;
    float* dst = dstBase + c;
    dst[(lane)      * 12] = e0 * inv;
    dst[(lane + 32) * 12] = e1 * inv;
    dst[(lane + 64) * 12] = e2 * inv;
    if (lane < 4) dst[(lane + 96) * 12] = e3 * inv;
}

// A softmax for one (g,j,d) -> sTdst[j*72 + c*8 + d]
__device__ __forceinline__ void asoftmax_one(int g, int j, int d,
                                             const float* __restrict__ A,
                                             float* __restrict__ sTdst) {
    float v[8]; float mx = -1e30f;
#pragma unroll
    for (int c = 0; c < 8; ++c) { v[c] = A[c * 128 + d * 16 + j * 4 + g]; mx = fmaxf(mx, v[c]); }
    float s = 0.f;
#pragma unroll
    for (int c = 0; c < 8; ++c) { v[c] = __expf(v[c] - mx); s += v[c]; }
    float inv = 1.f / s;
#pragma unroll
    for (int c = 0; c < 8; ++c) sTdst[j * 72 + c * 8 + d] = v[c] * inv;
}

// ================ single fused kernel ================
__global__ void __launch_bounds__(256, 4) k_all(const int* __restrict__ x,
                                                const float* __restrict__ A,
                                                const float* __restrict__ Bm,
                                                const float* __restrict__ Pi,
                                                float* __restrict__ out) {
    __shared__ __align__(16) float sT[288];          // own g: [j*72 + c*8 + d]
    __shared__ __align__(16) float sB[1200];         // own g: [sym*12 + c]
    __shared__ __align__(16) float pool[7616];       // phase-aliased
    __shared__ unsigned int sLast;

    // pool carving:
    //   phase A : sU  = pool+0    (4800)  [(j*100+v)*12 + d]  UNNORMALIZED
    //             sB6 = pool+4800 (2560)  [n6l*10 + d], n6l 0..255
    //             sE6 = pool+7360 (256)
    //   phase B : sB4 = pool+0 (160)  sE4 = pool+160 (16)  (sB6/sE6 read-only)
    //   tail    : sT2 = pool+0 (1152)  sB2t = pool+1152 (4800)  sPi = pool+5952 (32)
    float* const sU  = pool;
    float* const sB6 = pool + 4800;
    float* const sE6 = pool + 7360;
    float* const sB4 = pool;
    float* const sE4 = pool + 160;

    int g   = blockIdx.x >> 7;
    int blk = blockIdx.x & 127;
    int t   = threadIdx.x;
    int w = t >> 5, lane = t & 31;
    int grp = lane >> 3, d = lane & 7;

    // ---- prep: own g tables ----
    if (w < 8) bsoftmax_warp(g, w, lane, Bm, sB);
    if (t < 32) asoftmax_one(g, t >> 3, t & 7, A, sT);
    __syncthreads();

    // ---- leaf-lift table U (unnormalized) for own g ----
    for (int job = t; job < 400; job += 256) {
        int j = job / 100, v = job - 100 * j;
        float e[8];
#pragma unroll
        for (int c = 0; c < 8; ++c) e[c] = sB[v * 12 + c];
        float* dst = &sU[(j * 100 + v) * 12];
#pragma unroll
        for (int dd = 0; dd < 8; ++dd) {
            float acc = 0.f;
#pragma unroll
            for (int c = 0; c < 8; ++c) acc = fmaf(sT[j * 72 + c * 8 + dd], e[c], acc);
            dst[dd] = acc;
        }
    }
    __syncthreads();

    // ---- phase A: levels 8,7,6 ; thread per n6 (256 per block) ----
    {
        int n6 = (blk << 8) + t;
        // batched upfront loads (MLP=6)
        int v6 = __ldg(&x[OFF6 + n6]);
        int4 x7 = *reinterpret_cast<const int4*>(&x[OFF7 + 4 * n6]);
        const int4* px8 = reinterpret_cast<const int4*>(&x[OFF8 + 16 * n6]);
        int4 w8[4] = { px8[0], px8[1], px8[2], px8[3] };
        int v7a[4] = { x7.x, x7.y, x7.z, x7.w };

        float p6[8]; emload(sB, v6, p6);
        float ell = 0.f;

#pragma unroll
        for (int j7 = 0; j7 < 4; ++j7) {
            float p[8];
            leafprod(sB, sU, v7a[j7], w8[j7], p);
            float nu  = sum8r(p);
            ell      += __logf(nu);
            float inv = __fdividef(1.f, nu);
            float m[8]; matvecS(&sT[j7 * 72], p, m);
#pragma unroll
            for (int dd = 0; dd < 8; ++dd) p6[dd] *= m[dd] * inv;
        }
        float nu6  = sum8r(p6);
        ell       += __logf(nu6);
        float inv6 = __fdividef(1.f, nu6);
#pragma unroll
        for (int dd = 0; dd < 8; ++dd) sB6[t * 10 + dd] = p6[dd] * inv6;
        sE6[t] = ell;
    }
    __syncthreads();

    // ---- phase B: levels 6->5->4 ; warp per n4 (8 warps x 2) -> sB4 ----
    {
#pragma unroll 1
        for (int i = 0; i < 2; ++i) {
            int n4l = w * 2 + i;                 // 0..15
            int n4g = (blk << 4) + n4l;
            int n5g = 4 * n4g + grp;

            float p = sB[__ldg(&x[OFF5 + n5g]) * 12 + d];
            float ell = 0.f;
#pragma unroll
            for (int j6 = 0; j6 < 4; ++j6) {
                int n6l = 16 * n4l + 4 * grp + j6;
                float b = sB6[n6l * 10 + d];
                ell += sE6[n6l];
                p *= groupMatvec(&sT[j6 * 72], b, d);
            }
            float nu = groupSum8(p);
            ell += __logf(nu);
            p *= __fdividef(1.f, nu);

            float m = groupMatvec(&sT[grp * 72], p, d);
            m   *= __shfl_xor_sync(0xffffffffu, m, 8);
            ell += __shfl_xor_sync(0xffffffffu, ell, 8);
            m   *= __shfl_xor_sync(0xffffffffu, m, 16);
            ell += __shfl_xor_sync(0xffffffffu, ell, 16);

            float p4 = sB[__ldg(&x[OFF4 + n4g]) * 12 + d] * m;
            float nu4 = groupSum8(p4);
            ell += __logf(nu4);
            p4 *= __fdividef(1.f, nu4);

            if (grp == 0)  sB4[n4l * 10 + d] = p4;
            if (lane == 0) sE4[n4l] = ell;
        }
    }
    __syncthreads();

    // ---- phase C: levels 4->3->2 ; warp 0 -> gmem ----
    if (w == 0) {
        int n2g = blk;                               // 0..127
        int n3g = 4 * n2g + grp;

        float p = sB[__ldg(&x[OFF3 + n3g]) * 12 + d];
        float ell = 0.f;
#pragma unroll
        for (int j4 = 0; j4 < 4; ++j4) {
            int n4l = 4 * grp + j4;
            float b = sB4[n4l * 10 + d];
            ell += sE4[n4l];
            p *= groupMatvec(&sT[j4 * 72], b, d);
        }
        float nu = groupSum8(p);
        ell += __logf(nu);
        p *= __fdividef(1.f, nu);

        float m = groupMatvec(&sT[grp * 72], p, d);
        m   *= __shfl_xor_sync(0xffffffffu, m, 8);
        ell += __shfl_xor_sync(0xffffffffu, ell, 8);
        m   *= __shfl_xor_sync(0xffffffffu, m, 16);
        ell += __shfl_xor_sync(0xffffffffu, ell, 16);

        float p2 = sB[__ldg(&x[OFF2 + n2g]) * 12 + d] * m;
        float nu2 = groupSum8(p2);
        ell += __logf(nu2);
        p2 *= __fdividef(1.f, nu2);

        if (grp == 0)  g_beta2[((size_t)g * N2 + n2g) * 8 + d] = p2;
        if (lane == 0) g_ell2[(size_t)g * N2 + n2g] = ell;
    }
    __syncthreads();

    // ---- arrival: last block does the tail ----
    __threadfence();
    if (t == 0) {
        unsigned int prev = atomicAdd(&g_ctr, 1u);
        sLast = (prev == NBLK - 1) ? 1u : 0u;
    }
    __syncthreads();
    if (!sLast) return;

    // ======== tail (single block): levels 2->1->0 + Pi for all (g,tree) ========
    float* const sT2  = pool;            // 4*288
    float* const sB2t = pool + 1152;     // 4*1200
    float* const sPi  = pool + 5952;     // 4*8

    {
        for (int rep = 0; rep < 4; ++rep) {
            int job = w + 8 * rep;               // 0..31 -> (c = job>>2, g = job&3)
            bsoftmax_warp(job & 3, job >> 2, lane, Bm, sB2t + (job & 3) * 1200);
        }
        if (t < 128) {
            int gg = t >> 5, rem = t & 31;
            asoftmax_one(gg, rem >> 3, rem & 7, A, sT2 + gg * 288);
        } else if (t < 132) {
            int gg = t - 128;
            float v[8]; float mx = -1e30f;
#pragma unroll
            for (int c = 0; c < 8; ++c) { v[c] = Pi[c * 4 + gg]; mx = fmaxf(mx, v[c]); }
            float s = 0.f;
#pragma unroll
            for (int c = 0; c < 8; ++c) { v[c] = __expf(v[c] - mx); s += v[c]; }
            float inv = 1.f / s;
#pragma unroll
            for (int c = 0; c < 8; ++c) sPi[gg * 8 + c] = v[c] * inv;
        }
    }
    __syncthreads();

#pragma unroll 1
    for (int rep = 0; rep < 4; ++rep) {
        int idx = w * 4 + rep;                   // 0..31
        int gg = idx >> 3, tree = idx & 7;
        const float* Bt = sB2t + gg * 1200;
        const float* Tt = sT2 + gg * 288;
        int n1 = 4 * tree + grp;

        float p = Bt[__ldg(&x[OFF1 + n1]) * 12 + d];
        float ell = 0.f;
#pragma unroll
        for (int j2 = 0; j2 < 4; ++j2) {
            int n2 = 4 * n1 + j2;
            float b = __ldcg(&g_beta2[((size_t)gg * N2 + n2) * 8 + d]);
            ell += __ldcg(&g_ell2[(size_t)gg * N2 + n2]);
            p *= groupMatvec(&Tt[j2 * 72], b, d);
        }
        float nu = groupSum8(p);
        ell += __logf(nu);
        p *= __fdividef(1.f, nu);

        float m = groupMatvec(&Tt[grp * 72], p, d);
        m   *= __shfl_xor_sync(0xffffffffu, m, 8);
        ell += __shfl_xor_sync(0xffffffffu, ell, 8);
        m   *= __shfl_xor_sync(0xffffffffu, m, 16);
        ell += __shfl_xor_sync(0xffffffffu, ell, 16);

        float p0 = Bt[__ldg(&x[OFF0 + tree]) * 12 + d] * m;
        float nu0 = groupSum8(p0);
        ell += __logf(nu0);
        p0 *= __fdividef(1.f, nu0);

        float Z = groupSum8(sPi[gg * 8 + d] * p0);
        if (lane == 0) out[tree * NGEN + gg] = __logf(Z) + ell;
    }

    __syncthreads();
    if (t == 0) g_ctr = 0;      // reset for next graph replay
}

// ---------------- launcher ----------------
extern "C" void kernel_launch(void* const* d_in, const int* in_sizes, int n_in,
                              void* d_out, int out_size) {
    const int*   x  = nullptr;
    const float* A  = nullptr;
    const float* Bm = nullptr;
    const float* Pi = nullptr;
    for (int i = 0; i < n_in; ++i) {
        switch (in_sizes[i]) {
            case DIMX: x  = (const int*)  d_in[i]; break;
            case 1024: A  = (const float*)d_in[i]; break;
            case 3200: Bm = (const float*)d_in[i]; break;
            case 32:   Pi = (const float*)d_in[i]; break;
            default: break;
        }
    }
    k_all<<<NBLK, 256>>>(x, A, Bm, Pi, (float*)d_out);
}

// round 13
// speedup vs baseline: 1.6263x; 1.1722x over previous
#include <cuda_runtime.h>

// ---------------- problem constants ----------------
#define NGEN  4
#define NSYM  100
// level offsets into x (cumsum of 8*4^l)
#define OFF0 0
#define OFF1 8
#define OFF2 40
#define OFF3 168
#define OFF4 680
#define OFF5 2728
#define OFF6 10920
#define OFF7 43688
#define OFF8 174760
#define DIMX 699048

#define N2 128
#define NBLK 512     // 4 g x 128

#define USCALE 1048576.0f            // 2^20 per U entry
#define LOGADJ 221.8070977791825f    // 320 * ln2  (4 groups x 4 factors x 20 bits)

// ---------------- scratch (static device, no allocs) ----------------
__device__ float g_beta2[(size_t)NGEN * N2 * 8];
__device__ float g_ell2 [(size_t)NGEN * N2];
__device__ unsigned int g_ctr = 0;

// ---------------- bf16 helpers ----------------
__device__ __forceinline__ unsigned pack_bf16x2(float lo, float hi) {
    unsigned r;
    asm("cvt.rn.bf16x2.f32 %0, %1, %2;" : "=r"(r) : "f"(hi), "f"(lo));
    return r;
}
__device__ __forceinline__ unsigned bmul(unsigned a, unsigned b) {
    unsigned r;
    asm("mul.bf16x2 %0, %1, %2;" : "=r"(r) : "r"(a), "r"(b));
    return r;
}
__device__ __forceinline__ void unpack2(unsigned r, float& lo, float& hi) {
    lo = __uint_as_float(r << 16);
    hi = __uint_as_float(r & 0xffff0000u);
}

// ---------------- fp32 helpers ----------------
// m[d] = sum_c sTj[c*8+d] * r[c]
__device__ __forceinline__ void matvecS(const float* __restrict__ sTj, const float r[8], float m[8]) {
    const float4* T4 = reinterpret_cast<const float4*>(sTj);
#pragma unroll
    for (int c = 0; c < 8; ++c) {
        float4 t0 = T4[2 * c];
        float4 t1 = T4[2 * c + 1];
        float rc = r[c];
        if (c == 0) {
            m[0] = t0.x * rc; m[1] = t0.y * rc; m[2] = t0.z * rc; m[3] = t0.w * rc;
            m[4] = t1.x * rc; m[5] = t1.y * rc; m[6] = t1.z * rc; m[7] = t1.w * rc;
        } else {
            m[0] = fmaf(t0.x, rc, m[0]); m[1] = fmaf(t0.y, rc, m[1]);
            m[2] = fmaf(t0.z, rc, m[2]); m[3] = fmaf(t0.w, rc, m[3]);
            m[4] = fmaf(t1.x, rc, m[4]); m[5] = fmaf(t1.y, rc, m[5]);
            m[6] = fmaf(t1.z, rc, m[6]); m[7] = fmaf(t1.w, rc, m[7]);
        }
    }
}

__device__ __forceinline__ float sum8r(const float v[8]) {
    return ((v[0] + v[1]) + (v[2] + v[3])) + ((v[4] + v[5]) + (v[6] + v[7]));
}

__device__ __forceinline__ float groupSum8(float v) {
    v += __shfl_xor_sync(0xffffffffu, v, 4, 8);
    v += __shfl_xor_sync(0xffffffffu, v, 2, 8);
    v += __shfl_xor_sync(0xffffffffu, v, 1, 8);
    return v;
}

__device__ __forceinline__ float groupMatvec(const float* __restrict__ sTj, float bhat, int d) {
    float m = 0.f;
#pragma unroll
    for (int c = 0; c < 8; ++c) {
        float bc = __shfl_sync(0xffffffffu, bhat, c, 8);
        m = fmaf(sTj[c * 8 + d], bc, m);
    }
    return m;
}

// B softmax for one (g,c) by one warp -> dstBase[sym*12 + c]
__device__ __forceinline__ void bsoftmax_warp(int g, int c, int lane,
                                              const float* __restrict__ Bm,
                                              float* __restrict__ dstBase) {
    const float* src = Bm + c * 400 + g;
    float v0 = src[(lane)      * 4];
    float v1 = src[(lane + 32) * 4];
    float v2 = src[(lane + 64) * 4];
    float v3 = (lane < 4) ? src[(lane + 96) * 4] : -1e30f;
    float mx = fmaxf(fmaxf(v0, v1), fmaxf(v2, v3));
#pragma unroll
    for (int off = 16; off >= 1; off >>= 1)
        mx = fmaxf(mx, __shfl_xor_sync(0xffffffffu, mx, off));
    float e0 = __expf(v0 - mx), e1 = __expf(v1 - mx), e2 = __expf(v2 - mx);
    float e3 = (lane < 4) ? __expf(v3 - mx) : 0.f;
    float s = e0 + e1 + e2 + e3;
#pragma unroll
    for (int off = 16; off >= 1; off >>= 1)
        s += __shfl_xor_sync(0xffffffffu, s, off);
    float inv = 1.f / s;
    float* dst = dstBase + c;
    dst[(lane)      * 12] = e0 * inv;
    dst[(lane + 32) * 12] = e1 * inv;
    dst[(lane + 64) * 12] = e2 * inv;
    if (lane < 4) dst[(lane + 96) * 12] = e3 * inv;
}

// A softmax for one (g,j,d) -> sTdst[j*72 + c*8 + d]
__device__ __forceinline__ void asoftmax_one(int g, int j, int d,
                                             const float* __restrict__ A,
                                             float* __restrict__ sTdst) {
    float v[8]; float mx = -1e30f;
#pragma unroll
    for (int c = 0; c < 8; ++c) { v[c] = A[c * 128 + d * 16 + j * 4 + g]; mx = fmaxf(mx, v[c]); }
    float s = 0.f;
#pragma unroll
    for (int c = 0; c < 8; ++c) { v[c] = __expf(v[c] - mx); s += v[c]; }
    float inv = 1.f / s;
#pragma unroll
    for (int c = 0; c < 8; ++c) sTdst[j * 72 + c * 8 + d] = v[c] * inv;
}

// ================ single fused kernel ================
__global__ void __launch_bounds__(256, 4) k_all(const int* __restrict__ x,
                                                const float* __restrict__ A,
                                                const float* __restrict__ Bm,
                                                const float* __restrict__ Pi,
                                                float* __restrict__ out) {
    __shared__ __align__(16) float sT[288];          // own g: [j*72 + c*8 + d]
    __shared__ __align__(16) float sB[1200];         // own g: [sym*12 + c] fp32 (phases B/C)
    __shared__ __align__(16) float pool[5984];       // phase-aliased
    __shared__ unsigned int sLast;

    // pool carving (float units):
    //   phase A : sUh = pool+0    (1600 uints = 400 x uint4)  bf16x2 U, scaled 2^20
    //             sBh = pool+1600 (400 uints = 100 x uint4)   bf16x2 emissions
    //             sB6 = pool+2000 (2560)  [n6l*10 + d]
    //             sE6 = pool+4560 (256)
    //   phase B : sB4 = pool+0 (160)  sE4 = pool+160 (16)  (sB6/sE6 read-only)
    //   tail    : sT2 = pool+0 (1152)  sB2t = pool+1152 (4800)  sPi = pool+5952 (32)
    uint4* const sUh4 = reinterpret_cast<uint4*>(pool);
    uint4* const sBh4 = reinterpret_cast<uint4*>(pool + 1600);
    float* const sB6  = pool + 2000;
    float* const sE6  = pool + 4560;
    float* const sB4  = pool;
    float* const sE4  = pool + 160;

    int g   = blockIdx.x >> 7;
    int blk = blockIdx.x & 127;
    int t   = threadIdx.x;
    int w = t >> 5, lane = t & 31;
    int grp = lane >> 3, d = lane & 7;

    // ---- prep: own g tables ----
    if (w < 8) bsoftmax_warp(g, w, lane, Bm, sB);
    if (t < 32) asoftmax_one(g, t >> 3, t & 7, A, sT);
    __syncthreads();

    // ---- leaf-lift table U (bf16, scaled) + emission table (bf16) ----
    for (int job = t; job < 400; job += 256) {
        int j = job / 100, v = job - 100 * j;
        float e[8];
#pragma unroll
        for (int c = 0; c < 8; ++c) e[c] = sB[v * 12 + c] * USCALE;
        float acc[8];
#pragma unroll
        for (int dd = 0; dd < 8; ++dd) {
            float a = 0.f;
#pragma unroll
            for (int c = 0; c < 8; ++c) a = fmaf(sT[j * 72 + c * 8 + dd], e[c], a);
            acc[dd] = a;
        }
        sUh4[j * 100 + v] = make_uint4(pack_bf16x2(acc[0], acc[1]),
                                       pack_bf16x2(acc[2], acc[3]),
                                       pack_bf16x2(acc[4], acc[5]),
                                       pack_bf16x2(acc[6], acc[7]));
    }
    if (t < 100) {
        float e[8];
#pragma unroll
        for (int c = 0; c < 8; ++c) e[c] = sB[t * 12 + c];
        sBh4[t] = make_uint4(pack_bf16x2(e[0], e[1]), pack_bf16x2(e[2], e[3]),
                             pack_bf16x2(e[4], e[5]), pack_bf16x2(e[6], e[7]));
    }
    __syncthreads();

    // ---- phase A: levels 8,7,6 ; thread per n6 (256 per block) ----
    {
        int n6 = (blk << 8) + t;
        // batched upfront loads (MLP=6)
        int v6 = __ldg(&x[OFF6 + n6]);
        int4 x7 = *reinterpret_cast<const int4*>(&x[OFF7 + 4 * n6]);
        const int4* px8 = reinterpret_cast<const int4*>(&x[OFF8 + 16 * n6]);
        int4 w8[4] = { px8[0], px8[1], px8[2], px8[3] };
        int v7a[4] = { x7.x, x7.y, x7.z, x7.w };

        float p6[8];
        {
            uint4 e6 = sBh4[v6];
            unpack2(e6.x, p6[0], p6[1]); unpack2(e6.y, p6[2], p6[3]);
            unpack2(e6.z, p6[4], p6[5]); unpack2(e6.w, p6[6], p6[7]);
        }
        float ell = 0.f;

#pragma unroll
        for (int j7 = 0; j7 < 4; ++j7) {
            int4 v8 = w8[j7];
            uint4 e  = sBh4[v7a[j7]];
            uint4 u0 = sUh4[        v8.x];
            uint4 u1 = sUh4[100 + v8.y];
            uint4 u2 = sUh4[200 + v8.z];
            uint4 u3 = sUh4[300 + v8.w];

            unsigned r0 = bmul(bmul(bmul(u0.x, u1.x), bmul(u2.x, u3.x)), e.x);
            unsigned r1 = bmul(bmul(bmul(u0.y, u1.y), bmul(u2.y, u3.y)), e.y);
            unsigned r2 = bmul(bmul(bmul(u0.z, u1.z), bmul(u2.z, u3.z)), e.z);
            unsigned r3 = bmul(bmul(bmul(u0.w, u1.w), bmul(u2.w, u3.w)), e.w);

            float p[8];
            unpack2(r0, p[0], p[1]); unpack2(r1, p[2], p[3]);
            unpack2(r2, p[4], p[5]); unpack2(r3, p[6], p[7]);

            float nu  = sum8r(p);
            ell      += __logf(nu);
            float inv = __fdividef(1.f, nu);
            float m[8]; matvecS(&sT[j7 * 72], p, m);
#pragma unroll
            for (int dd = 0; dd < 8; ++dd) p6[dd] *= m[dd] * inv;
        }
        float nu6  = sum8r(p6);
        ell       += __logf(nu6) - LOGADJ;
        float inv6 = __fdividef(1.f, nu6);
#pragma unroll
        for (int dd = 0; dd < 8; ++dd) sB6[t * 10 + dd] = p6[dd] * inv6;
        sE6[t] = ell;
    }
    __syncthreads();

    // ---- phase B: levels 6->5->4 ; warp per n4 (8 warps x 2) -> sB4 ----
    {
#pragma unroll 1
        for (int i = 0; i < 2; ++i) {
            int n4l = w * 2 + i;                 // 0..15
            int n4g = (blk << 4) + n4l;
            int n5g = 4 * n4g + grp;

            float p = sB[__ldg(&x[OFF5 + n5g]) * 12 + d];
            float ell = 0.f;
#pragma unroll
            for (int j6 = 0; j6 < 4; ++j6) {
                int n6l = 16 * n4l + 4 * grp + j6;
                float b = sB6[n6l * 10 + d];
                ell += sE6[n6l];
                p *= groupMatvec(&sT[j6 * 72], b, d);
            }
            float nu = groupSum8(p);
            ell += __logf(nu);
            p *= __fdividef(1.f, nu);

            float m = groupMatvec(&sT[grp * 72], p, d);
            m   *= __shfl_xor_sync(0xffffffffu, m, 8);
            ell += __shfl_xor_sync(0xffffffffu, ell, 8);
            m   *= __shfl_xor_sync(0xffffffffu, m, 16);
            ell += __shfl_xor_sync(0xffffffffu, ell, 16);

            float p4 = sB[__ldg(&x[OFF4 + n4g]) * 12 + d] * m;
            float nu4 = groupSum8(p4);
            ell += __logf(nu4);
            p4 *= __fdividef(1.f, nu4);

            if (grp == 0)  sB4[n4l * 10 + d] = p4;
            if (lane == 0) sE4[n4l] = ell;
        }
    }
    __syncthreads();

    // ---- phase C: levels 4->3->2 ; warp 0 -> gmem ----
    if (w == 0) {
        int n2g = blk;                               // 0..127
        int n3g = 4 * n2g + grp;

        float p = sB[__ldg(&x[OFF3 + n3g]) * 12 + d];
        float ell = 0.f;
#pragma unroll
        for (int j4 = 0; j4 < 4; ++j4) {
            int n4l = 4 * grp + j4;
            float b = sB4[n4l * 10 + d];
            ell += sE4[n4l];
            p *= groupMatvec(&sT[j4 * 72], b, d);
        }
        float nu = groupSum8(p);
        ell += __logf(nu);
        p *= __fdividef(1.f, nu);

        float m = groupMatvec(&sT[grp * 72], p, d);
        m   *= __shfl_xor_sync(0xffffffffu, m, 8);
        ell += __shfl_xor_sync(0xffffffffu, ell, 8);
        m   *= __shfl_xor_sync(0xffffffffu, m, 16);
        ell += __shfl_xor_sync(0xffffffffu, ell, 16);

        float p2 = sB[__ldg(&x[OFF2 + n2g]) * 12 + d] * m;
        float nu2 = groupSum8(p2);
        ell += __logf(nu2);
        p2 *= __fdividef(1.f, nu2);

        if (grp == 0)  g_beta2[((size_t)g * N2 + n2g) * 8 + d] = p2;
        if (lane == 0) g_ell2[(size_t)g * N2 + n2g] = ell;
    }
    __syncthreads();

    // ---- arrival: last block does the tail ----
    __threadfence();
    if (t == 0) {
        unsigned int prev = atomicAdd(&g_ctr, 1u);
        sLast = (prev == NBLK - 1) ? 1u : 0u;
    }
    __syncthreads();
    if (!sLast) return;

    // ======== tail (single block): levels 2->1->0 + Pi for all (g,tree) ========
    float* const sT2  = pool;            // 4*288
    float* const sB2t = pool + 1152;     // 4*1200
    float* const sPi  = pool + 5952;     // 4*8

    {
        for (int rep = 0; rep < 4; ++rep) {
            int job = w + 8 * rep;               // 0..31 -> (c = job>>2, g = job&3)
            bsoftmax_warp(job & 3, job >> 2, lane, Bm, sB2t + (job & 3) * 1200);
        }
        if (t < 128) {
            int gg = t >> 5, rem = t & 31;
            asoftmax_one(gg, rem >> 3, rem & 7, A, sT2 + gg * 288);
        } else if (t < 132) {
            int gg = t - 128;
            float v[8]; float mx = -1e30f;
#pragma unroll
            for (int c = 0; c < 8; ++c) { v[c] = Pi[c * 4 + gg]; mx = fmaxf(mx, v[c]); }
            float s = 0.f;
#pragma unroll
            for (int c = 0; c < 8; ++c) { v[c] = __expf(v[c] - mx); s += v[c]; }
            float inv = 1.f / s;
#pragma unroll
            for (int c = 0; c < 8; ++c) sPi[gg * 8 + c] = v[c] * inv;
        }
    }
    __syncthreads();

#pragma unroll 1
    for (int rep = 0; rep < 4; ++rep) {
        int idx = w * 4 + rep;                   // 0..31
        int gg = idx >> 3, tree = idx & 7;
        const float* Bt = sB2t + gg * 1200;
        const float* Tt = sT2 + gg * 288;
        int n1 = 4 * tree + grp;

        float p = Bt[__ldg(&x[OFF1 + n1]) * 12 + d];
        float ell = 0.f;
#pragma unroll
        for (int j2 = 0; j2 < 4; ++j2) {
            int n2 = 4 * n1 + j2;
            float b = __ldcg(&g_beta2[((size_t)gg * N2 + n2) * 8 + d]);
            ell += __ldcg(&g_ell2[(size_t)gg * N2 + n2]);
            p *= groupMatvec(&Tt[j2 * 72], b, d);
        }
        float nu = groupSum8(p);
        ell += __logf(nu);
        p *= __fdividef(1.f, nu);

        float m = groupMatvec(&Tt[grp * 72], p, d);
        m   *= __shfl_xor_sync(0xffffffffu, m, 8);
        ell += __shfl_xor_sync(0xffffffffu, ell, 8);
        m   *= __shfl_xor_sync(0xffffffffu, m, 16);
        ell += __shfl_xor_sync(0xffffffffu, ell, 16);

        float p0 = Bt[__ldg(&x[OFF0 + tree]) * 12 + d] * m;
        float nu0 = groupSum8(p0);
        ell += __logf(nu0);
        p0 *= __fdividef(1.f, nu0);

        float Z = groupSum8(sPi[gg * 8 + d] * p0);
        if (lane == 0) out[tree * NGEN + gg] = __logf(Z) + ell;
    }

    __syncthreads();
    if (t == 0) g_ctr = 0;      // reset for next graph replay
}

// ---------------- launcher ----------------
extern "C" void kernel_launch(void* const* d_in, const int* in_sizes, int n_in,
                              void* d_out, int out_size) {
    const int*   x  = nullptr;
    const float* A  = nullptr;
    const float* Bm = nullptr;
    const float* Pi = nullptr;
    for (int i = 0; i < n_in; ++i) {
        switch (in_sizes[i]) {
            case DIMX: x  = (const int*)  d_in[i]; break;
            case 1024: A  = (const float*)d_in[i]; break;
            case 3200: Bm = (const float*)d_in[i]; break;
            case 32:   Pi = (const float*)d_in[i]; break;
            default: break;
        }
    }
    k_all<<<NBLK, 256>>>(x, A, Bm, Pi, (float*)d_out);
}

// round 15
// speedup vs baseline: 1.6558x; 1.0182x over previous
#include <cuda_runtime.h>

// ---------------- problem constants ----------------
#define NGEN  4
#define NSYM  100
// level offsets into x (cumsum of 8*4^l)
#define OFF0 0
#define OFF1 8
#define OFF2 40
#define OFF3 168
#define OFF4 680
#define OFF5 2728
#define OFF6 10920
#define OFF7 43688
#define OFF8 174760
#define DIMX 699048

#define N2 128
#define NBLK 512     // 4 g x 128

#define USCALE 1048576.0f            // 2^20 per U entry
#define LOGADJ 221.8070977791825f    // 320 * ln2

// ---------------- scratch (static device, no allocs) ----------------
__device__ float g_beta2[(size_t)NGEN * N2 * 8];
__device__ float g_ell2 [(size_t)NGEN * N2];
__device__ unsigned int g_ctr = 0;

// ---------------- bf16 helpers ----------------
__device__ __forceinline__ unsigned pack_bf16x2(float lo, float hi) {
    unsigned r;
    asm("cvt.rn.bf16x2.f32 %0, %1, %2;" : "=r"(r) : "f"(hi), "f"(lo));
    return r;
}
__device__ __forceinline__ unsigned bmul(unsigned a, unsigned b) {
    unsigned r;
    asm("mul.bf16x2 %0, %1, %2;" : "=r"(r) : "r"(a), "r"(b));
    return r;
}
__device__ __forceinline__ unsigned bfma(unsigned a, unsigned b, unsigned c) {
    unsigned r;
    asm("fma.rn.bf16x2 %0, %1, %2, %3;" : "=r"(r) : "r"(a), "r"(b), "r"(c));
    return r;
}
__device__ __forceinline__ void unpack2(unsigned r, float& lo, float& hi) {
    lo = __uint_as_float(r << 16);
    hi = __uint_as_float(r & 0xffff0000u);
}

// ---------------- fp32 helpers ----------------
__device__ __forceinline__ float sum8r(const float v[8]) {
    return ((v[0] + v[1]) + (v[2] + v[3])) + ((v[4] + v[5]) + (v[6] + v[7]));
}

__device__ __forceinline__ float groupSum8(float v) {
    v += __shfl_xor_sync(0xffffffffu, v, 4, 8);
    v += __shfl_xor_sync(0xffffffffu, v, 2, 8);
    v += __shfl_xor_sync(0xffffffffu, v, 1, 8);
    return v;
}

__device__ __forceinline__ float groupMatvec(const float* __restrict__ sTj, float bhat, int d) {
    float m = 0.f;
#pragma unroll
    for (int c = 0; c < 8; ++c) {
        float bc = __shfl_sync(0xffffffffu, bhat, c, 8);
        m = fmaf(sTj[c * 8 + d], bc, m);
    }
    return m;
}

// B softmax for one (g,c) by one warp -> dstBase[sym*12 + c]
__device__ __forceinline__ void bsoftmax_warp(int g, int c, int lane,
                                              const float* __restrict__ Bm,
                                              float* __restrict__ dstBase) {
    const float* src = Bm + c * 400 + g;
    float v0 = src[(lane)      * 4];
    float v1 = src[(lane + 32) * 4];
    float v2 = src[(lane + 64) * 4];
    float v3 = (lane < 4) ? src[(lane + 96) * 4] : -1e30f;
    float mx = fmaxf(fmaxf(v0, v1), fmaxf(v2, v3));
#pragma unroll
    for (int off = 16; off >= 1; off >>= 1)
        mx = fmaxf(mx, __shfl_xor_sync(0xffffffffu, mx, off));
    float e0 = __expf(v0 - mx), e1 = __expf(v1 - mx), e2 = __expf(v2 - mx);
    float e3 = (lane < 4) ? __expf(v3 - mx) : 0.f;
    float s = e0 + e1 + e2 + e3;
#pragma unroll
    for (int off = 16; off >= 1; off >>= 1)
        s += __shfl_xor_sync(0xffffffffu, s, off);
    float inv = 1.f / s;
    float* dst = dstBase + c;
    dst[(lane)      * 12] = e0 * inv;
    dst[(lane + 32) * 12] = e1 * inv;
    dst[(lane + 64) * 12] = e2 * inv;
    if (lane < 4) dst[(lane + 96) * 12] = e3 * inv;
}

// A softmax for one (g,j,d) -> sTdst[j*72 + c*8 + d]
__device__ __forceinline__ void asoftmax_one(int g, int j, int d,
                                             const float* __restrict__ A,
                                             float* __restrict__ sTdst) {
    float v[8]; float mx = -1e30f;
#pragma unroll
    for (int c = 0; c < 8; ++c) { v[c] = A[c * 128 + d * 16 + j * 4 + g]; mx = fmaxf(mx, v[c]); }
    float s = 0.f;
#pragma unroll
    for (int c = 0; c < 8; ++c) { v[c] = __expf(v[c] - mx); s += v[c]; }
    float inv = 1.f / s;
#pragma unroll
    for (int c = 0; c < 8; ++c) sTdst[j * 72 + c * 8 + d] = v[c] * inv;
}

// ================ single fused kernel ================
__global__ void __launch_bounds__(256, 4) k_all(const int* __restrict__ x,
                                                const float* __restrict__ A,
                                                const float* __restrict__ Bm,
                                                const float* __restrict__ Pi,
                                                float* __restrict__ out) {
    __shared__ __align__(16) float sT[288];          // own g: [j*72 + c*8 + d] fp32
    __shared__ __align__(16) unsigned sT2h[128];     // own g: [j*8 + c] -> uint4 of bf16x2 d-pairs
    __shared__ __align__(16) float sB[1200];         // own g: [sym*12 + c] fp32 (phases B/C)
    __shared__ __align__(16) float pool[5984];       // phase-aliased
    __shared__ unsigned int sLast;

    uint4* const sT2h4 = reinterpret_cast<uint4*>(sT2h);
    // pool carving (float units):
    //   phase A : sUh = pool+0 (1600u = 400 uint4)  sBh = pool+1600 (400u = 100 uint4)
    //             sB6 = pool+2000 (2560)  sE6 = pool+4560 (256)
    //   phase B : sB4 = pool+0 (160)  sE4 = pool+160 (16)
    //   tail    : sT2 = pool+0 (1152)  sB2t = pool+1152 (4800)  sPi = pool+5952 (32)
    uint4* const sUh4 = reinterpret_cast<uint4*>(pool);
    uint4* const sBh4 = reinterpret_cast<uint4*>(pool + 1600);
    float* const sB6  = pool + 2000;
    float* const sE6  = pool + 4560;
    float* const sB4  = pool;
    float* const sE4  = pool + 160;

    int g   = blockIdx.x >> 7;
    int blk = blockIdx.x & 127;
    int t   = threadIdx.x;
    int w = t >> 5, lane = t & 31;
    int grp = lane >> 3, d = lane & 7;

    // ---- prep: own g tables ----
    if (w < 8) bsoftmax_warp(g, w, lane, Bm, sB);
    if (t < 32) asoftmax_one(g, t >> 3, t & 7, A, sT);
    __syncthreads();

    // ---- pack T to bf16x2 (t<32: one (j,c) each) ----
    if (t < 32) {
        int j = t >> 3, c = t & 7;
        const float* Ts = &sT[j * 72 + c * 8];
        sT2h4[j * 8 + c] = make_uint4(pack_bf16x2(Ts[0], Ts[1]), pack_bf16x2(Ts[2], Ts[3]),
                                      pack_bf16x2(Ts[4], Ts[5]), pack_bf16x2(Ts[6], Ts[7]));
    }

    // ---- leaf-lift table U (bf16, scaled) + emission table (bf16) ----
    for (int job = t; job < 400; job += 256) {
        int j = job / 100, v = job - 100 * j;
        float e[8];
#pragma unroll
        for (int c = 0; c < 8; ++c) e[c] = sB[v * 12 + c] * USCALE;
        float acc[8];
#pragma unroll
        for (int dd = 0; dd < 8; ++dd) {
            float a = 0.f;
#pragma unroll
            for (int c = 0; c < 8; ++c) a = fmaf(sT[j * 72 + c * 8 + dd], e[c], a);
            acc[dd] = a;
        }
        sUh4[j * 100 + v] = make_uint4(pack_bf16x2(acc[0], acc[1]),
                                       pack_bf16x2(acc[2], acc[3]),
                                       pack_bf16x2(acc[4], acc[5]),
                                       pack_bf16x2(acc[6], acc[7]));
    }
    if (t < 100) {
        float e[8];
#pragma unroll
        for (int c = 0; c < 8; ++c) e[c] = sB[t * 12 + c];
        sBh4[t] = make_uint4(pack_bf16x2(e[0], e[1]), pack_bf16x2(e[2], e[3]),
                             pack_bf16x2(e[4], e[5]), pack_bf16x2(e[6], e[7]));
    }
    __syncthreads();

    // ---- phase A: levels 8,7,6 ; thread per n6 (256 per block) ----
    {
        int n6 = (blk << 8) + t;
        int v6 = __ldg(&x[OFF6 + n6]);
        int4 x7 = *reinterpret_cast<const int4*>(&x[OFF7 + 4 * n6]);
        const int4* px8 = reinterpret_cast<const int4*>(&x[OFF8 + 16 * n6]);
        int4 w8[4] = { px8[0], px8[1], px8[2], px8[3] };
        int v7a[4] = { x7.x, x7.y, x7.z, x7.w };

        float p6[8];
        {
            uint4 e6 = sBh4[v6];
            unpack2(e6.x, p6[0], p6[1]); unpack2(e6.y, p6[2], p6[3]);
            unpack2(e6.z, p6[4], p6[5]); unpack2(e6.w, p6[6], p6[7]);
        }
        float ell = 0.f;

#pragma unroll
        for (int j7 = 0; j7 < 4; ++j7) {
            int4 v8 = w8[j7];
            uint4 e  = sBh4[v7a[j7]];
            uint4 u0 = sUh4[      v8.x];
            uint4 u1 = sUh4[100 + v8.y];
            uint4 u2 = sUh4[200 + v8.z];
            uint4 u3 = sUh4[300 + v8.w];

            unsigned r0 = bmul(bmul(bmul(u0.x, u1.x), bmul(u2.x, u3.x)), e.x);
            unsigned r1 = bmul(bmul(bmul(u0.y, u1.y), bmul(u2.y, u3.y)), e.y);
            unsigned r2 = bmul(bmul(bmul(u0.z, u1.z), bmul(u2.z, u3.z)), e.z);
            unsigned r3 = bmul(bmul(bmul(u0.w, u1.w), bmul(u2.w, u3.w)), e.w);

            float p[8];
            unpack2(r0, p[0], p[1]); unpack2(r1, p[2], p[3]);
            unpack2(r2, p[4], p[5]); unpack2(r3, p[6], p[7]);

            float nu  = sum8r(p);
            ell      += __logf(nu);
            float inv = __fdividef(1.f, nu);

            // bf16 matvec: m2[q] = sum_c T2[c][q] * dup(p[c])
            const uint4* Tj = sT2h4 + j7 * 8;
            unsigned m0, m1, m2, m3;
            {
                uint4 tc = Tj[0];
                unsigned pd = pack_bf16x2(p[0], p[0]);
                m0 = bmul(tc.x, pd); m1 = bmul(tc.y, pd);
                m2 = bmul(tc.z, pd); m3 = bmul(tc.w, pd);
            }
#pragma unroll
            for (int c = 1; c < 8; ++c) {
                uint4 tc = Tj[c];
                unsigned pd = pack_bf16x2(p[c], p[c]);
                m0 = bfma(tc.x, pd, m0); m1 = bfma(tc.y, pd, m1);
                m2 = bfma(tc.z, pd, m2); m3 = bfma(tc.w, pd, m3);
            }
            float mf[8];
            unpack2(m0, mf[0], mf[1]); unpack2(m1, mf[2], mf[3]);
            unpack2(m2, mf[4], mf[5]); unpack2(m3, mf[6], mf[7]);
#pragma unroll
            for (int dd = 0; dd < 8; ++dd) p6[dd] *= mf[dd] * inv;
        }
        float nu6  = sum8r(p6);
        ell       += __logf(nu6) - LOGADJ;
        float inv6 = __fdividef(1.f, nu6);
#pragma unroll
        for (int dd = 0; dd < 8; ++dd) sB6[t * 10 + dd] = p6[dd] * inv6;
        sE6[t] = ell;
    }
    __syncthreads();

    // ---- phase B: levels 6->5->4 ; warp per n4 (8 warps x 2) -> sB4 ----
    {
#pragma unroll 1
        for (int i = 0; i < 2; ++i) {
            int n4l = w * 2 + i;                 // 0..15
            int n4g = (blk << 4) + n4l;
            int n5g = 4 * n4g + grp;

            float p = sB[__ldg(&x[OFF5 + n5g]) * 12 + d];
            float ell = 0.f;
#pragma unroll
            for (int j6 = 0; j6 < 4; ++j6) {
                int n6l = 16 * n4l + 4 * grp + j6;
                float b = sB6[n6l * 10 + d];
                ell += sE6[n6l];
                p *= groupMatvec(&sT[j6 * 72], b, d);
            }
            float nu = groupSum8(p);
            ell += __logf(nu);
            p *= __fdividef(1.f, nu);

            float m = groupMatvec(&sT[grp * 72], p, d);
            m   *= __shfl_xor_sync(0xffffffffu, m, 8);
            ell += __shfl_xor_sync(0xffffffffu, ell, 8);
            m   *= __shfl_xor_sync(0xffffffffu, m, 16);
            ell += __shfl_xor_sync(0xffffffffu, ell, 16);

            float p4 = sB[__ldg(&x[OFF4 + n4g]) * 12 + d] * m;
            float nu4 = groupSum8(p4);
            ell += __logf(nu4);
            p4 *= __fdividef(1.f, nu4);

            if (grp == 0)  sB4[n4l * 10 + d] = p4;
            if (lane == 0) sE4[n4l] = ell;
        }
    }
    __syncthreads();

    // ---- phase C: levels 4->3->2 ; warp 0 -> gmem ----
    if (w == 0) {
        int n2g = blk;                               // 0..127
        int n3g = 4 * n2g + grp;

        float p = sB[__ldg(&x[OFF3 + n3g]) * 12 + d];
        float ell = 0.f;
#pragma unroll
        for (int j4 = 0; j4 < 4; ++j4) {
            int n4l = 4 * grp + j4;
            float b = sB4[n4l * 10 + d];
            ell += sE4[n4l];
            p *= groupMatvec(&sT[j4 * 72], b, d);
        }
        float nu = groupSum8(p);
        ell += __logf(nu);
        p *= __fdividef(1.f, nu);

        float m = groupMatvec(&sT[grp * 72], p, d);
        m   *= __shfl_xor_sync(0xffffffffu, m, 8);
        ell += __shfl_xor_sync(0xffffffffu, ell, 8);
        m   *= __shfl_xor_sync(0xffffffffu, m, 16);
        ell += __shfl_xor_sync(0xffffffffu, ell, 16);

        float p2 = sB[__ldg(&x[OFF2 + n2g]) * 12 + d] * m;
        float nu2 = groupSum8(p2);
        ell += __logf(nu2);
        p2 *= __fdividef(1.f, nu2);

        if (grp == 0)  g_beta2[((size_t)g * N2 + n2g) * 8 + d] = p2;
        if (lane == 0) g_ell2[(size_t)g * N2 + n2g] = ell;
    }
    __syncthreads();

    // ---- arrival: last block does the tail ----
    __threadfence();
    if (t == 0) {
        unsigned int prev = atomicAdd(&g_ctr, 1u);
        sLast = (prev == NBLK - 1) ? 1u : 0u;
    }
    __syncthreads();
    if (!sLast) return;

    // ======== tail (single block): levels 2->1->0 + Pi for all (g,tree) ========
    float* const sT2t = pool;            // 4*288
    float* const sB2t = pool + 1152;     // 4*1200
    float* const sPi  = pool + 5952;     // 4*8

    {
        for (int rep = 0; rep < 4; ++rep) {
            int job = w + 8 * rep;               // 0..31 -> (c = job>>2, g = job&3)
            bsoftmax_warp(job & 3, job >> 2, lane, Bm, sB2t + (job & 3) * 1200);
        }
        if (t < 128) {
            int gg = t >> 5, rem = t & 31;
            asoftmax_one(gg, rem >> 3, rem & 7, A, sT2t + gg * 288);
        } else if (t < 132) {
            int gg = t - 128;
            float v[8]; float mx = -1e30f;
#pragma unroll
            for (int c = 0; c < 8; ++c) { v[c] = Pi[c * 4 + gg]; mx = fmaxf(mx, v[c]); }
            float s = 0.f;
#pragma unroll
            for (int c = 0; c < 8; ++c) { v[c] = __expf(v[c] - mx); s += v[c]; }
            float inv = 1.f / s;
#pragma unroll
            for (int c = 0; c < 8; ++c) sPi[gg * 8 + c] = v[c] * inv;
        }
    }
    __syncthreads();

#pragma unroll 1
    for (int rep = 0; rep < 4; ++rep) {
        int idx = w * 4 + rep;                   // 0..31
        int gg = idx >> 3, tree = idx & 7;
        const float* Bt = sB2t + gg * 1200;
        const float* Tt = sT2t + gg * 288;
        int n1 = 4 * tree + grp;

        float p = Bt[__ldg(&x[OFF1 + n1]) * 12 + d];
        float ell = 0.f;
#pragma unroll
        for (int j2 = 0; j2 < 4; ++j2) {
            int n2 = 4 * n1 + j2;
            float b = __ldcg(&g_beta2[((size_t)gg * N2 + n2) * 8 + d]);
            ell += __ldcg(&g_ell2[(size_t)gg * N2 + n2]);
            p *= groupMatvec(&Tt[j2 * 72], b, d);
        }
        float nu = groupSum8(p);
        ell += __logf(nu);
        p *= __fdividef(1.f, nu);

        float m = groupMatvec(&Tt[grp * 72], p, d);
        m   *= __shfl_xor_sync(0xffffffffu, m, 8);
        ell += __shfl_xor_sync(0xffffffffu, ell, 8);
        m   *= __shfl_xor_sync(0xffffffffu, m, 16);
        ell += __shfl_xor_sync(0xffffffffu, ell, 16);

        float p0 = Bt[__ldg(&x[OFF0 + tree]) * 12 + d] * m;
        float nu0 = groupSum8(p0);
        ell += __logf(nu0);
        p0 *= __fdividef(1.f, nu0);

        float Z = groupSum8(sPi[gg * 8 + d] * p0);
        if (lane == 0) out[tree * NGEN + gg] = __logf(Z) + ell;
    }

    __syncthreads();
    if (t == 0) g_ctr = 0;      // reset for next graph replay
}

// ---------------- launcher ----------------
extern "C" void kernel_launch(void* const* d_in, const int* in_sizes, int n_in,
                              void* d_out, int out_size) {
    const int*   x  = nullptr;
    const float* A  = nullptr;
    const float* Bm = nullptr;
    const float* Pi = nullptr;
    for (int i = 0; i < n_in; ++i) {
        switch (in_sizes[i]) {
            case DIMX: x  = (const int*)  d_in[i]; break;
            case 1024: A  = (const float*)d_in[i]; break;
            case 3200: Bm = (const float*)d_in[i]; break;
            case 32:   Pi = (const float*)d_in[i]; break;
            default: break;
        }
    }
    k_all<<<NBLK, 256>>>(x, A, Bm, Pi, (float*)d_out);
}